// round 1
// baseline (speedup 1.0000x reference)
#include <cuda_runtime.h>
#include <math.h>

#define BATCH 4
#define HIMG 256
#define WIMG 256
#define CCH 128
#define TOK (BATCH*HIMG*WIMG)   // 262144
#define EPSV 1.001e-05f

// ---------------- scratch (static device arrays; no allocation) ----------------
__device__ float g_xw [ (size_t)TOK*CCH   ];   // LN1 + shifted window partition
__device__ float g_qkv[ (size_t)TOK*3*CCH ];   // qkv
__device__ float g_att[ (size_t)TOK*CCH   ];   // attention output (window layout)
__device__ float g_y1 [ (size_t)TOK*CCH   ];   // x + proj (image layout)
__device__ float g_h2 [ (size_t)TOK*CCH   ];   // LN2(y1)
__device__ float g_m1 [ (size_t)TOK*4*CCH ];   // gelu(h2@w1+b1)

// ---------------- LayerNorm (one warp per token), optional window permute ------
template<int PERM>
__global__ void ln_kernel(const float* __restrict__ x, const float* __restrict__ g,
                          const float* __restrict__ b, float* __restrict__ out) {
    int warp = threadIdx.x >> 5;
    int lane = threadIdx.x & 31;
    int t = blockIdx.x * 8 + warp;
    float4 v = ((const float4*)(x + (size_t)t * CCH))[lane];
    float s  = v.x + v.y + v.z + v.w;
    float sq = v.x*v.x + v.y*v.y + v.z*v.z + v.w*v.w;
    #pragma unroll
    for (int o = 16; o; o >>= 1) {
        s  += __shfl_xor_sync(0xffffffffu, s,  o);
        sq += __shfl_xor_sync(0xffffffffu, sq, o);
    }
    float mean = s * (1.0f / CCH);
    float var  = sq * (1.0f / CCH) - mean * mean;
    float rstd = rsqrtf(var + EPSV);
    float4 gv = ((const float4*)g)[lane];
    float4 bv = ((const float4*)b)[lane];
    float4 r;
    r.x = (v.x - mean) * rstd * gv.x + bv.x;
    r.y = (v.y - mean) * rstd * gv.y + bv.y;
    r.z = (v.z - mean) * rstd * gv.z + bv.z;
    r.w = (v.w - mean) * rstd * gv.w + bv.w;
    size_t ot;
    if (PERM) {
        // image coords -> shifted coords -> window token index
        int bi = t >> 16;
        int oh = (t >> 8) & 255;
        int ow = t & 255;
        int sh = (oh + 252) & 255;   // (oh - 4) mod 256
        int sw = (ow + 252) & 255;
        int wh = sh >> 3, ii = sh & 7;
        int wc = sw >> 3, jj = sw & 7;
        int win = (bi * 32 + wh) * 32 + wc;
        ot = (size_t)win * 64 + ii * 8 + jj;
    } else {
        ot = (size_t)t;
    }
    ((float4*)(out + ot * CCH))[lane] = r;
}

// ---------------- tiled SGEMM: C = A[M,K] @ B[K,N] + bias, fused epilogues -----
// BM=128, BN=64, BK=16, 256 threads, 8x4 per thread
#define GBM 128
#define GBN 64
#define GBK 16

__device__ __forceinline__ float gelu_exact(float x) {
    return 0.5f * x * (1.0f + erff(x * 0.70710678118654752f));
}

// EPI: 0 = bias only; 1 = proj (bias + window-reverse scatter + x residual);
//      2 = bias + GELU; 3 = bias + residual (same row)
template<int EPI>
__global__ void gemm_kernel(const float* __restrict__ A, const float* __restrict__ B,
                            const float* __restrict__ bias, const float* __restrict__ extra,
                            float* __restrict__ C, int M, int N, int K) {
    __shared__ float As[GBK][GBM];
    __shared__ float Bs[GBK][GBN];
    int tid = threadIdx.x;
    int bm = blockIdx.y * GBM;
    int bn = blockIdx.x * GBN;
    int tx = tid & 15;     // n direction
    int ty = tid >> 4;     // m direction

    float acc[8][4];
    #pragma unroll
    for (int i = 0; i < 8; i++)
        #pragma unroll
        for (int j = 0; j < 4; j++) acc[i][j] = 0.0f;

    for (int k0 = 0; k0 < K; k0 += GBK) {
        // load A tile (128x16) as float4 along K, store transposed
        #pragma unroll
        for (int r = 0; r < 2; r++) {
            int id = tid + r * 256;
            int m  = id >> 2;
            int kv = id & 3;
            float4 a = *(const float4*)(A + (size_t)(bm + m) * K + k0 + kv * 4);
            As[kv*4+0][m] = a.x; As[kv*4+1][m] = a.y;
            As[kv*4+2][m] = a.z; As[kv*4+3][m] = a.w;
        }
        // load B tile (16x64)
        {
            int kk = tid >> 4;
            int nv = tid & 15;
            float4 bb = *(const float4*)(B + (size_t)(k0 + kk) * N + bn + nv * 4);
            *(float4*)&Bs[kk][nv * 4] = bb;
        }
        __syncthreads();
        #pragma unroll
        for (int kk = 0; kk < GBK; kk++) {
            float ra[8], rb[4];
            #pragma unroll
            for (int i = 0; i < 8; i++) ra[i] = As[kk][ty * 8 + i];
            #pragma unroll
            for (int j = 0; j < 4; j++) rb[j] = Bs[kk][tx * 4 + j];
            #pragma unroll
            for (int i = 0; i < 8; i++)
                #pragma unroll
                for (int j = 0; j < 4; j++) acc[i][j] += ra[i] * rb[j];
        }
        __syncthreads();
    }

    int coln = bn + tx * 4;
    float4 bsv = *(const float4*)(bias + coln);
    #pragma unroll
    for (int i = 0; i < 8; i++) {
        int row = bm + ty * 8 + i;
        float4 v;
        v.x = acc[i][0] + bsv.x;
        v.y = acc[i][1] + bsv.y;
        v.z = acc[i][2] + bsv.z;
        v.w = acc[i][3] + bsv.w;
        if (EPI == 0) {
            *(float4*)(C + (size_t)row * N + coln) = v;
        } else if (EPI == 1) {
            // window-reverse + unshift + residual with original x
            int win = row >> 6, r6 = row & 63;
            int bi = win >> 10, wim = win & 1023;
            int wh = wim >> 5, wc = wim & 31;
            int ii = r6 >> 3, jj = r6 & 7;
            int oh = (wh * 8 + ii + 4) & 255;
            int ow = (wc * 8 + jj + 4) & 255;
            size_t orow = ((size_t)(bi * 256 + oh) * 256 + ow);
            float4 xres = *(const float4*)(extra + orow * 128 + coln);
            v.x += xres.x; v.y += xres.y; v.z += xres.z; v.w += xres.w;
            *(float4*)(C + orow * 128 + coln) = v;
        } else if (EPI == 2) {
            v.x = gelu_exact(v.x); v.y = gelu_exact(v.y);
            v.z = gelu_exact(v.z); v.w = gelu_exact(v.w);
            *(float4*)(C + (size_t)row * N + coln) = v;
        } else { // EPI == 3
            float4 res = *(const float4*)(extra + (size_t)row * 128 + coln);
            v.x += res.x; v.y += res.y; v.z += res.z; v.w += res.w;
            *(float4*)(C + (size_t)row * 128 + coln) = v;
        }
    }
}

// ---------------- windowed attention: one block per (window, head) -------------
// 64 threads; thread i owns query row i -> softmax is thread-local.
__global__ void attn_kernel(const float* __restrict__ qkv, const float* __restrict__ rpb,
                            float* __restrict__ out) {
    int win = blockIdx.x;
    int h   = blockIdx.y;
    int i   = threadIdx.x;   // 0..63

    __shared__ float ks[64][32];
    __shared__ float vs[64][32];
    __shared__ float at[64][65];
    __shared__ float tbl[15 * 15 * 4];
    __shared__ int   lab[64];

    for (int p = i; p < 900; p += 64) tbl[p] = rpb[p];
    // K/V tiles for this head: 64 rows x 32 cols each, float4 loads
    for (int p = i; p < 512; p += 64) {
        int row = p >> 3, c4 = p & 7;
        size_t base = (size_t)(win * 64 + row) * 384 + h * 32 + c4 * 4;
        *(float4*)&ks[row][c4 * 4] = *(const float4*)(qkv + base + 128);
        *(float4*)&vs[row][c4 * 4] = *(const float4*)(qkv + base + 256);
    }
    // region labels on unshifted partition grid (mask)
    {
        int wim = win & 1023;
        int wh = wim >> 5, wc = wim & 31;
        int r = wh * 8 + (i >> 3);
        int c = wc * 8 + (i & 7);
        int rr = (r < 248) ? 0 : ((r < 252) ? 1 : 2);
        int rc = (c < 248) ? 0 : ((c < 252) ? 1 : 2);
        lab[i] = rr * 3 + rc;
    }
    float q[32];
    {
        size_t base = (size_t)(win * 64 + i) * 384 + h * 32;
        #pragma unroll
        for (int d4 = 0; d4 < 8; d4++) {
            float4 qq = *(const float4*)(qkv + base + d4 * 4);
            q[d4*4+0] = qq.x * 0.17677669529663687f;
            q[d4*4+1] = qq.y * 0.17677669529663687f;
            q[d4*4+2] = qq.z * 0.17677669529663687f;
            q[d4*4+3] = qq.w * 0.17677669529663687f;
        }
    }
    __syncthreads();

    int ih = i >> 3, iw = i & 7;
    int li = lab[i];
    float mx = -1e30f;
    for (int j = 0; j < 64; j++) {
        float s = 0.0f;
        #pragma unroll
        for (int d = 0; d < 32; d++) s += q[d] * ks[j][d];
        int jh = j >> 3, jw = j & 7;
        s += tbl[((ih - jh + 7) * 15 + (iw - jw + 7)) * 4 + h];
        if (lab[j] != li) s -= 100.0f;
        at[i][j] = s;
        mx = fmaxf(mx, s);
    }
    float sum = 0.0f;
    for (int j = 0; j < 64; j++) {
        float e = __expf(at[i][j] - mx);
        at[i][j] = e;
        sum += e;
    }
    float inv = 1.0f / sum;
    float o[32];
    #pragma unroll
    for (int d = 0; d < 32; d++) o[d] = 0.0f;
    for (int j = 0; j < 64; j++) {
        float a = at[i][j];
        #pragma unroll
        for (int d = 0; d < 32; d++) o[d] += a * vs[j][d];
    }
    size_t ob = (size_t)(win * 64 + i) * 128 + h * 32;
    #pragma unroll
    for (int d4 = 0; d4 < 8; d4++) {
        float4 w4;
        w4.x = o[d4*4+0] * inv; w4.y = o[d4*4+1] * inv;
        w4.z = o[d4*4+2] * inv; w4.w = o[d4*4+3] * inv;
        *(float4*)(out + ob + d4 * 4) = w4;
    }
}

// ---------------- launch ----------------
extern "C" void kernel_launch(void* const* d_in, const int* in_sizes, int n_in,
                              void* d_out, int out_size) {
    const float* x      = (const float*)d_in[0];
    const float* gamma1 = (const float*)d_in[1];
    const float* beta1  = (const float*)d_in[2];
    const float* qkv_w  = (const float*)d_in[3];
    const float* qkv_b  = (const float*)d_in[4];
    const float* proj_w = (const float*)d_in[5];
    const float* proj_b = (const float*)d_in[6];
    const float* rpb    = (const float*)d_in[7];
    const float* gamma2 = (const float*)d_in[8];
    const float* beta2  = (const float*)d_in[9];
    const float* w1     = (const float*)d_in[10];
    const float* b1     = (const float*)d_in[11];
    const float* w2     = (const float*)d_in[12];
    const float* b2     = (const float*)d_in[13];
    float* out = (float*)d_out;

    float* xw  = nullptr; float* qkv = nullptr; float* att = nullptr;
    float* y1  = nullptr; float* h2  = nullptr; float* m1  = nullptr;
    cudaGetSymbolAddress((void**)&xw,  g_xw);
    cudaGetSymbolAddress((void**)&qkv, g_qkv);
    cudaGetSymbolAddress((void**)&att, g_att);
    cudaGetSymbolAddress((void**)&y1,  g_y1);
    cudaGetSymbolAddress((void**)&h2,  g_h2);
    cudaGetSymbolAddress((void**)&m1,  g_m1);

    // 1. LN1 + shift + window partition
    ln_kernel<1><<<TOK / 8, 256>>>(x, gamma1, beta1, xw);
    // 2. qkv GEMM  [T,128]@[128,384]
    gemm_kernel<0><<<dim3(384 / GBN, TOK / GBM), 256>>>(xw, qkv_w, qkv_b, nullptr, qkv, TOK, 384, 128);
    // 3. window attention
    attn_kernel<<<dim3(4096, 4), 64>>>(qkv, rpb, att);
    // 4. proj GEMM + window reverse + residual  -> y1 (image layout)
    gemm_kernel<1><<<dim3(128 / GBN, TOK / GBM), 256>>>(att, proj_w, proj_b, x, y1, TOK, 128, 128);
    // 5. LN2
    ln_kernel<0><<<TOK / 8, 256>>>(y1, gamma2, beta2, h2);
    // 6. fc1 + GELU  [T,128]@[128,512]
    gemm_kernel<2><<<dim3(512 / GBN, TOK / GBM), 256>>>(h2, w1, b1, nullptr, m1, TOK, 512, 128);
    // 7. fc2 + residual  [T,512]@[512,128] -> out
    gemm_kernel<3><<<dim3(128 / GBN, TOK / GBM), 256>>>(m1, w2, b2, y1, out, TOK, 128, 512);
}

// round 4
// speedup vs baseline: 2.8439x; 2.8439x over previous
#include <cuda_runtime.h>
#include <cuda_bf16.h>
#include <math.h>
#include <cstdint>

#define BATCH 4
#define HIMG 256
#define WIMG 256
#define CCH 128
#define TOK (BATCH*HIMG*WIMG)   // 262144
#define EPSV 1.001e-05f

// ---------------- scratch (static device arrays; no allocation) ----------------
__device__ __align__(16) __nv_bfloat16 g_xw [ (size_t)TOK*CCH   ];
__device__ __align__(16) __nv_bfloat16 g_qkv[ (size_t)TOK*3*CCH ];
__device__ __align__(16) __nv_bfloat16 g_att[ (size_t)TOK*CCH   ];
__device__ __align__(16) float         g_y1 [ (size_t)TOK*CCH   ];
__device__ __align__(16) __nv_bfloat16 g_h2 [ (size_t)TOK*CCH   ];
__device__ __align__(16) __nv_bfloat16 g_m1 [ (size_t)TOK*4*CCH ];
// bf16 weights, same [K][N] row-major layout as the fp32 originals
__device__ __align__(16) __nv_bfloat16 g_wq [ 128*384 ];
__device__ __align__(16) __nv_bfloat16 g_wp [ 128*128 ];
__device__ __align__(16) __nv_bfloat16 g_w1b[ 128*512 ];
__device__ __align__(16) __nv_bfloat16 g_w2b[ 512*128 ];

// ---------------- helpers ----------------
__device__ __forceinline__ uint32_t smem_u32(const void* p) {
    uint32_t a;
    asm("{ .reg .u64 t; cvta.to.shared.u64 t, %1; cvt.u32.u64 %0, t; }" : "=r"(a) : "l"(p));
    return a;
}
__device__ __forceinline__ uint32_t pack_bf16(float lo, float hi) {
    uint32_t r;
    asm("cvt.rn.bf16x2.f32 %0, %1, %2;" : "=r"(r) : "f"(hi), "f"(lo));
    return r;
}
__device__ __forceinline__ void cp_async16(uint32_t dst, const void* src) {
    asm volatile("cp.async.cg.shared.global [%0], [%1], 16;" :: "r"(dst), "l"(src));
}
__device__ __forceinline__ void cp_commit() { asm volatile("cp.async.commit_group;"); }
template<int N>
__device__ __forceinline__ void cp_wait() { asm volatile("cp.async.wait_group %0;" :: "n"(N)); }

__device__ __forceinline__ void ldm_x4(uint32_t* r, uint32_t a) {
    asm volatile("ldmatrix.sync.aligned.m8n8.x4.shared.b16 {%0,%1,%2,%3}, [%4];"
        : "=r"(r[0]), "=r"(r[1]), "=r"(r[2]), "=r"(r[3]) : "r"(a));
}
__device__ __forceinline__ void ldm_x4_t(uint32_t* r, uint32_t a) {
    asm volatile("ldmatrix.sync.aligned.m8n8.x4.trans.shared.b16 {%0,%1,%2,%3}, [%4];"
        : "=r"(r[0]), "=r"(r[1]), "=r"(r[2]), "=r"(r[3]) : "r"(a));
}
__device__ __forceinline__ void mma16816(float* d, const uint32_t* a, uint32_t b0, uint32_t b1) {
    asm volatile("mma.sync.aligned.m16n8k16.row.col.f32.bf16.bf16.f32 "
        "{%0,%1,%2,%3}, {%4,%5,%6,%7}, {%8,%9}, {%0,%1,%2,%3};"
        : "+f"(d[0]), "+f"(d[1]), "+f"(d[2]), "+f"(d[3])
        : "r"(a[0]), "r"(a[1]), "r"(a[2]), "r"(a[3]), "r"(b0), "r"(b1));
}
// SW128 swizzle on 16B granules (base must be 128B aligned)
__device__ __forceinline__ uint32_t swz(uint32_t off) { return off ^ (((off >> 7) & 7) << 4); }

__device__ __forceinline__ float gelu_exact(float x) {
    return 0.5f * x * (1.0f + erff(x * 0.70710678118654752f));
}

// ---------------- fp32 -> bf16 weight convert (layout preserved) ---------------
__global__ void convw_kernel(const float* __restrict__ w, __nv_bfloat16* __restrict__ wt, int n4) {
    int i = blockIdx.x * 256 + threadIdx.x;
    if (i >= n4) return;
    float4 v = ((const float4*)w)[i];
    uint2 p;
    p.x = pack_bf16(v.x, v.y);
    p.y = pack_bf16(v.z, v.w);
    *(uint2*)(wt + (size_t)i * 4) = p;
}

// ---------------- LayerNorm (one warp per token), optional window permute ------
template<int PERM>
__global__ void ln_kernel(const float* __restrict__ x, const float* __restrict__ g,
                          const float* __restrict__ b, __nv_bfloat16* __restrict__ out) {
    int warp = threadIdx.x >> 5;
    int lane = threadIdx.x & 31;
    int t = blockIdx.x * 8 + warp;
    float4 v = ((const float4*)(x + (size_t)t * CCH))[lane];
    float s  = v.x + v.y + v.z + v.w;
    float sq = v.x*v.x + v.y*v.y + v.z*v.z + v.w*v.w;
    #pragma unroll
    for (int o = 16; o; o >>= 1) {
        s  += __shfl_xor_sync(0xffffffffu, s,  o);
        sq += __shfl_xor_sync(0xffffffffu, sq, o);
    }
    float mean = s * (1.0f / CCH);
    float var  = sq * (1.0f / CCH) - mean * mean;
    float rstd = rsqrtf(var + EPSV);
    float4 gv = ((const float4*)g)[lane];
    float4 bv = ((const float4*)b)[lane];
    float rx = (v.x - mean) * rstd * gv.x + bv.x;
    float ry = (v.y - mean) * rstd * gv.y + bv.y;
    float rz = (v.z - mean) * rstd * gv.z + bv.z;
    float rw = (v.w - mean) * rstd * gv.w + bv.w;
    size_t ot;
    if (PERM) {
        int bi = t >> 16;
        int oh = (t >> 8) & 255;
        int ow = t & 255;
        int sh = (oh + 252) & 255;
        int sw = (ow + 252) & 255;
        int wh = sh >> 3, ii = sh & 7;
        int wc = sw >> 3, jj = sw & 7;
        int win = (bi * 32 + wh) * 32 + wc;
        ot = (size_t)win * 64 + ii * 8 + jj;
    } else {
        ot = (size_t)t;
    }
    uint2 pk;
    pk.x = pack_bf16(rx, ry);
    pk.y = pack_bf16(rz, rw);
    *(uint2*)(out + ot * CCH + lane * 4) = pk;
}

// ---------------- HMMA bf16 GEMM: BM=128 BN=64 BK=32, 256 thr, double-buffered -
// A: bf16 [M,K] row-major. Bw: bf16 [K,N] row-major. N also = C row stride.
// EPI: 0 = bias -> bf16 C ; 1 = bias + window-reverse + x residual -> fp32 C
//      2 = bias + GELU -> bf16 C ; 3 = bias + residual(extra) -> fp32 C
template<int EPI, int K, int N>
__global__ __launch_bounds__(256) void tgemm(
    const __nv_bfloat16* __restrict__ A, const __nv_bfloat16* __restrict__ Bw,
    const float* __restrict__ bias, const float* __restrict__ extra, void* __restrict__ Cout)
{
    __shared__ __align__(128) __nv_bfloat16 As[2][128 * 32];  // 8KB each
    __shared__ __align__(128) __nv_bfloat16 Bs[2][32 * 64];   // 4KB each

    const int tid  = threadIdx.x;
    const int lane = tid & 31;
    const int wid  = tid >> 5;
    const int wm   = wid & 3;     // 0..3 -> 32 rows each
    const int wn   = wid >> 2;    // 0..1 -> 32 cols each
    const int bm   = blockIdx.y * 128;
    const int bn   = blockIdx.x * 64;

    const uint32_t s_a0 = smem_u32(As[0]);
    const uint32_t s_b0 = smem_u32(Bs[0]);

    const int NCH = K / 32;

    // cp.async load of chunk c into buffer buf
    auto load_chunk = [&](int c, int buf) {
        uint32_t abase = s_a0 + buf * 8192;
        #pragma unroll
        for (int r = 0; r < 2; r++) {
            int s = tid + r * 256;        // 0..511
            int row = s >> 2, cs = s & 3;
            cp_async16(abase + swz(row * 64 + cs * 16),
                       A + (size_t)(bm + row) * K + c * 32 + cs * 8);
        }
        uint32_t bbase = s_b0 + buf * 4096;
        {
            int row = tid >> 3, cs = tid & 7;   // 32 rows x 8 segs
            cp_async16(bbase + swz(row * 128 + cs * 16),
                       Bw + (size_t)(c * 32 + row) * N + bn + cs * 8);
        }
    };

    float d[2][4][4];
    #pragma unroll
    for (int mi = 0; mi < 2; mi++)
        #pragma unroll
        for (int ni = 0; ni < 4; ni++)
            #pragma unroll
            for (int r = 0; r < 4; r++) d[mi][ni][r] = 0.0f;

    load_chunk(0, 0);
    cp_commit();

    const int lrow = lane & 15;
    const int lseg = lane >> 4;

    for (int c = 0; c < NCH; c++) {
        int buf = c & 1;
        if (c + 1 < NCH) {
            load_chunk(c + 1, buf ^ 1);
            cp_commit();
            cp_wait<1>();
        } else {
            cp_wait<0>();
        }
        __syncthreads();

        uint32_t abase = s_a0 + buf * 8192;
        uint32_t bbase = s_b0 + buf * 4096;
        #pragma unroll
        for (int ks = 0; ks < 2; ks++) {       // two k16 steps per BK=32
            uint32_t a[2][4];
            #pragma unroll
            for (int mi = 0; mi < 2; mi++) {
                int row = wm * 32 + mi * 16 + lrow;
                int seg = ks * 2 + lseg;
                ldm_x4(a[mi], abase + swz(row * 64 + seg * 16));
            }
            uint32_t b[2][4];
            #pragma unroll
            for (int bp = 0; bp < 2; bp++) {   // each covers 16 cols -> 2 n-tiles
                int row = ks * 16 + lrow;
                int seg = wn * 4 + bp * 2 + lseg;
                ldm_x4_t(b[bp], bbase + swz(row * 128 + seg * 16));
            }
            #pragma unroll
            for (int mi = 0; mi < 2; mi++)
                #pragma unroll
                for (int ni = 0; ni < 4; ni++)
                    mma16816(d[mi][ni], a[mi], b[ni >> 1][(ni & 1) * 2], b[ni >> 1][(ni & 1) * 2 + 1]);
        }
        __syncthreads();   // all done reading buf before it is refilled
    }

    // ---------------- epilogue ----------------
    const int l4 = lane >> 2, lm = lane & 3;
    float2 bs[4];
    #pragma unroll
    for (int ni = 0; ni < 4; ni++)
        bs[ni] = *(const float2*)(bias + bn + wn * 32 + ni * 8 + lm * 2);

    #pragma unroll
    for (int mi = 0; mi < 2; mi++) {
        #pragma unroll
        for (int half = 0; half < 2; half++) {
            int row = bm + wm * 32 + mi * 16 + half * 8 + l4;
            if (EPI == 0 || EPI == 2) {
                __nv_bfloat16* C = (__nv_bfloat16*)Cout;
                #pragma unroll
                for (int ni = 0; ni < 4; ni++) {
                    int col = bn + wn * 32 + ni * 8 + lm * 2;
                    float v0 = d[mi][ni][half * 2 + 0] + bs[ni].x;
                    float v1 = d[mi][ni][half * 2 + 1] + bs[ni].y;
                    if (EPI == 2) { v0 = gelu_exact(v0); v1 = gelu_exact(v1); }
                    *(uint32_t*)(C + (size_t)row * N + col) = pack_bf16(v0, v1);
                }
            } else if (EPI == 1) {
                float* C = (float*)Cout;
                int win = row >> 6, r6 = row & 63;
                int bi = win >> 10, wim = win & 1023;
                int wh = wim >> 5, wc = wim & 31;
                int ii = r6 >> 3, jj = r6 & 7;
                int oh = (wh * 8 + ii + 4) & 255;
                int ow = (wc * 8 + jj + 4) & 255;
                size_t orow = ((size_t)(bi * 256 + oh) * 256 + ow);
                #pragma unroll
                for (int ni = 0; ni < 4; ni++) {
                    int col = bn + wn * 32 + ni * 8 + lm * 2;
                    float2 xr = *(const float2*)(extra + orow * 128 + col);
                    float2 v;
                    v.x = d[mi][ni][half * 2 + 0] + bs[ni].x + xr.x;
                    v.y = d[mi][ni][half * 2 + 1] + bs[ni].y + xr.y;
                    *(float2*)(C + orow * 128 + col) = v;
                }
            } else { // EPI == 3
                float* C = (float*)Cout;
                #pragma unroll
                for (int ni = 0; ni < 4; ni++) {
                    int col = bn + wn * 32 + ni * 8 + lm * 2;
                    float2 res = *(const float2*)(extra + (size_t)row * 128 + col);
                    float2 v;
                    v.x = d[mi][ni][half * 2 + 0] + bs[ni].x + res.x;
                    v.y = d[mi][ni][half * 2 + 1] + bs[ni].y + res.y;
                    *(float2*)(C + (size_t)row * 128 + col) = v;
                }
            }
        }
    }
}

// ---------------- windowed attention: one block per (window, head) -------------
__global__ void attn_kernel(const __nv_bfloat16* __restrict__ qkv, const float* __restrict__ rpb,
                            __nv_bfloat16* __restrict__ out) {
    int win = blockIdx.x;
    int h   = blockIdx.y;
    int i   = threadIdx.x;   // 0..63

    __shared__ float ks[64][32];
    __shared__ float vs[64][32];
    __shared__ float at[64][65];
    __shared__ float tbl[15 * 15 * 4];
    __shared__ int   lab[64];

    for (int p = i; p < 900; p += 64) tbl[p] = rpb[p];
    for (int p = i; p < 256; p += 64) {
        int row = p >> 2, c8 = p & 3;
        size_t base = (size_t)(win * 64 + row) * 384 + h * 32 + c8 * 8;
        uint4 kk = *(const uint4*)(qkv + base + 128);
        uint4 vv = *(const uint4*)(qkv + base + 256);
        const __nv_bfloat162* kp = (const __nv_bfloat162*)&kk;
        const __nv_bfloat162* vp = (const __nv_bfloat162*)&vv;
        #pragma unroll
        for (int q2 = 0; q2 < 4; q2++) {
            float2 kf = __bfloat1622float2(kp[q2]);
            float2 vf = __bfloat1622float2(vp[q2]);
            ks[row][c8 * 8 + q2 * 2 + 0] = kf.x;
            ks[row][c8 * 8 + q2 * 2 + 1] = kf.y;
            vs[row][c8 * 8 + q2 * 2 + 0] = vf.x;
            vs[row][c8 * 8 + q2 * 2 + 1] = vf.y;
        }
    }
    {
        int wim = win & 1023;
        int wh = wim >> 5, wc = wim & 31;
        int r = wh * 8 + (i >> 3);
        int c = wc * 8 + (i & 7);
        int rr = (r < 248) ? 0 : ((r < 252) ? 1 : 2);
        int rc = (c < 248) ? 0 : ((c < 252) ? 1 : 2);
        lab[i] = rr * 3 + rc;
    }
    float q[32];
    {
        size_t base = (size_t)(win * 64 + i) * 384 + h * 32;
        #pragma unroll
        for (int c8 = 0; c8 < 4; c8++) {
            uint4 qq = *(const uint4*)(qkv + base + c8 * 8);
            const __nv_bfloat162* qp = (const __nv_bfloat162*)&qq;
            #pragma unroll
            for (int q2 = 0; q2 < 4; q2++) {
                float2 qf = __bfloat1622float2(qp[q2]);
                q[c8 * 8 + q2 * 2 + 0] = qf.x * 0.17677669529663687f;
                q[c8 * 8 + q2 * 2 + 1] = qf.y * 0.17677669529663687f;
            }
        }
    }
    __syncthreads();

    int ih = i >> 3, iw = i & 7;
    int li = lab[i];
    float mx = -1e30f;
    for (int j = 0; j < 64; j++) {
        float s = 0.0f;
        #pragma unroll
        for (int d = 0; d < 32; d++) s += q[d] * ks[j][d];
        int jh = j >> 3, jw = j & 7;
        s += tbl[((ih - jh + 7) * 15 + (iw - jw + 7)) * 4 + h];
        if (lab[j] != li) s -= 100.0f;
        at[i][j] = s;
        mx = fmaxf(mx, s);
    }
    float sum = 0.0f;
    for (int j = 0; j < 64; j++) {
        float e = __expf(at[i][j] - mx);
        at[i][j] = e;
        sum += e;
    }
    float inv = 1.0f / sum;
    float o[32];
    #pragma unroll
    for (int d = 0; d < 32; d++) o[d] = 0.0f;
    for (int j = 0; j < 64; j++) {
        float a = at[i][j];
        #pragma unroll
        for (int d = 0; d < 32; d++) o[d] += a * vs[j][d];
    }
    size_t ob = (size_t)(win * 64 + i) * 128 + h * 32;
    #pragma unroll
    for (int c8 = 0; c8 < 4; c8++) {
        uint4 pk;
        pk.x = pack_bf16(o[c8*8+0]*inv, o[c8*8+1]*inv);
        pk.y = pack_bf16(o[c8*8+2]*inv, o[c8*8+3]*inv);
        pk.z = pack_bf16(o[c8*8+4]*inv, o[c8*8+5]*inv);
        pk.w = pack_bf16(o[c8*8+6]*inv, o[c8*8+7]*inv);
        *(uint4*)(out + ob + c8 * 8) = pk;
    }
}

// ---------------- launch ----------------
extern "C" void kernel_launch(void* const* d_in, const int* in_sizes, int n_in,
                              void* d_out, int out_size) {
    const float* x      = (const float*)d_in[0];
    const float* gamma1 = (const float*)d_in[1];
    const float* beta1  = (const float*)d_in[2];
    const float* qkv_w  = (const float*)d_in[3];
    const float* qkv_b  = (const float*)d_in[4];
    const float* proj_w = (const float*)d_in[5];
    const float* proj_b = (const float*)d_in[6];
    const float* rpb    = (const float*)d_in[7];
    const float* gamma2 = (const float*)d_in[8];
    const float* beta2  = (const float*)d_in[9];
    const float* w1     = (const float*)d_in[10];
    const float* b1     = (const float*)d_in[11];
    const float* w2     = (const float*)d_in[12];
    const float* b2     = (const float*)d_in[13];
    float* out = (float*)d_out;

    __nv_bfloat16 *xw, *qkv, *att, *h2, *m1, *wq, *wp, *w1b, *w2b;
    float *y1;
    cudaGetSymbolAddress((void**)&xw,  g_xw);
    cudaGetSymbolAddress((void**)&qkv, g_qkv);
    cudaGetSymbolAddress((void**)&att, g_att);
    cudaGetSymbolAddress((void**)&y1,  g_y1);
    cudaGetSymbolAddress((void**)&h2,  g_h2);
    cudaGetSymbolAddress((void**)&m1,  g_m1);
    cudaGetSymbolAddress((void**)&wq,  g_wq);
    cudaGetSymbolAddress((void**)&wp,  g_wp);
    cudaGetSymbolAddress((void**)&w1b, g_w1b);
    cudaGetSymbolAddress((void**)&w2b, g_w2b);

    // bf16 weight conversion (layout preserved)
    convw_kernel<<<(128*384/4 + 255) / 256, 256>>>(qkv_w, wq, 128*384/4);
    convw_kernel<<<(128*128/4 + 255) / 256, 256>>>(proj_w, wp, 128*128/4);
    convw_kernel<<<(128*512/4 + 255) / 256, 256>>>(w1, w1b, 128*512/4);
    convw_kernel<<<(512*128/4 + 255) / 256, 256>>>(w2, w2b, 512*128/4);

    // 1. LN1 + shift + window partition (bf16)
    ln_kernel<1><<<TOK / 8, 256>>>(x, gamma1, beta1, xw);
    // 2. qkv GEMM  [T,128]@[128,384] -> bf16
    tgemm<0, 128, 384><<<dim3(6, TOK / 128), 256>>>(xw, wq, qkv_b, nullptr, qkv);
    // 3. window attention (bf16 in/out)
    attn_kernel<<<dim3(4096, 4), 64>>>(qkv, rpb, att);
    // 4. proj GEMM + window reverse + residual -> y1 fp32 (image layout)
    tgemm<1, 128, 128><<<dim3(2, TOK / 128), 256>>>(att, wp, proj_b, x, y1);
    // 5. LN2 -> bf16
    ln_kernel<0><<<TOK / 8, 256>>>(y1, gamma2, beta2, h2);
    // 6. fc1 + GELU  [T,128]@[128,512] -> bf16
    tgemm<2, 128, 512><<<dim3(8, TOK / 128), 256>>>(h2, w1b, b1, nullptr, m1);
    // 7. fc2 + residual  [T,512]@[512,128] -> fp32 out
    tgemm<3, 512, 128><<<dim3(2, TOK / 128), 256>>>(m1, w2b, b2, y1, out);
}

// round 5
// speedup vs baseline: 4.2480x; 1.4937x over previous
#include <cuda_runtime.h>
#include <cuda_bf16.h>
#include <math.h>
#include <cstdint>

#define BATCH 4
#define HIMG 256
#define WIMG 256
#define CCH 128
#define TOK (BATCH*HIMG*WIMG)   // 262144
#define EPSV 1.001e-05f

// ---------------- scratch (static device arrays; no allocation) ----------------
__device__ __align__(16) __nv_bfloat16 g_xw [ (size_t)TOK*CCH   ];
__device__ __align__(16) __nv_bfloat16 g_qkv[ (size_t)TOK*3*CCH ];
__device__ __align__(16) __nv_bfloat16 g_att[ (size_t)TOK*CCH   ];
__device__ __align__(16) float         g_y1 [ (size_t)TOK*CCH   ];
__device__ __align__(16) __nv_bfloat16 g_h2 [ (size_t)TOK*CCH   ];
__device__ __align__(16) __nv_bfloat16 g_m1 [ (size_t)TOK*4*CCH ];
// bf16 weights, same [K][N] row-major layout as the fp32 originals
__device__ __align__(16) __nv_bfloat16 g_wq [ 128*384 ];
__device__ __align__(16) __nv_bfloat16 g_wp [ 128*128 ];
__device__ __align__(16) __nv_bfloat16 g_w1b[ 128*512 ];
__device__ __align__(16) __nv_bfloat16 g_w2b[ 512*128 ];

// ---------------- helpers ----------------
__device__ __forceinline__ uint32_t smem_u32(const void* p) {
    uint32_t a;
    asm("{ .reg .u64 t; cvta.to.shared.u64 t, %1; cvt.u32.u64 %0, t; }" : "=r"(a) : "l"(p));
    return a;
}
__device__ __forceinline__ uint32_t pack_bf16(float lo, float hi) {
    uint32_t r;
    asm("cvt.rn.bf16x2.f32 %0, %1, %2;" : "=r"(r) : "f"(hi), "f"(lo));
    return r;
}
__device__ __forceinline__ void cp_async16(uint32_t dst, const void* src) {
    asm volatile("cp.async.cg.shared.global [%0], [%1], 16;" :: "r"(dst), "l"(src));
}
__device__ __forceinline__ void cp_commit() { asm volatile("cp.async.commit_group;"); }
template<int N>
__device__ __forceinline__ void cp_wait() { asm volatile("cp.async.wait_group %0;" :: "n"(N)); }

__device__ __forceinline__ void ldm_x4(uint32_t* r, uint32_t a) {
    asm volatile("ldmatrix.sync.aligned.m8n8.x4.shared.b16 {%0,%1,%2,%3}, [%4];"
        : "=r"(r[0]), "=r"(r[1]), "=r"(r[2]), "=r"(r[3]) : "r"(a));
}
__device__ __forceinline__ void ldm_x4_t(uint32_t* r, uint32_t a) {
    asm volatile("ldmatrix.sync.aligned.m8n8.x4.trans.shared.b16 {%0,%1,%2,%3}, [%4];"
        : "=r"(r[0]), "=r"(r[1]), "=r"(r[2]), "=r"(r[3]) : "r"(a));
}
__device__ __forceinline__ void mma16816(float* d, const uint32_t* a, uint32_t b0, uint32_t b1) {
    asm volatile("mma.sync.aligned.m16n8k16.row.col.f32.bf16.bf16.f32 "
        "{%0,%1,%2,%3}, {%4,%5,%6,%7}, {%8,%9}, {%0,%1,%2,%3};"
        : "+f"(d[0]), "+f"(d[1]), "+f"(d[2]), "+f"(d[3])
        : "r"(a[0]), "r"(a[1]), "r"(a[2]), "r"(a[3]), "r"(b0), "r"(b1));
}
__device__ __forceinline__ float gelu_exact(float x) {
    return 0.5f * x * (1.0f + erff(x * 0.70710678118654752f));
}

// ---------------- fp32 -> bf16 weight convert, all 4 weights in one launch -----
__global__ void convw_kernel(const float* __restrict__ w0, __nv_bfloat16* __restrict__ t0,
                             const float* __restrict__ w1, __nv_bfloat16* __restrict__ t1,
                             const float* __restrict__ w2, __nv_bfloat16* __restrict__ t2,
                             const float* __restrict__ w3, __nv_bfloat16* __restrict__ t3) {
    // sizes in float4 units: 12288, 4096, 16384, 16384 (total 49152)
    int i = blockIdx.x * 256 + threadIdx.x;
    const float* w; __nv_bfloat16* t; int base;
    if (i < 12288)      { w = w0; t = t0; base = 0; }
    else if (i < 16384) { w = w1; t = t1; base = 12288; }
    else if (i < 32768) { w = w2; t = t2; base = 16384; }
    else                { w = w3; t = t3; base = 32768; }
    int j = i - base;
    float4 v = ((const float4*)w)[j];
    uint2 p;
    p.x = pack_bf16(v.x, v.y);
    p.y = pack_bf16(v.z, v.w);
    *(uint2*)(t + (size_t)j * 4) = p;
}

// ---------------- LayerNorm (one warp per token), optional window permute ------
template<int PERM>
__global__ void ln_kernel(const float* __restrict__ x, const float* __restrict__ g,
                          const float* __restrict__ b, __nv_bfloat16* __restrict__ out) {
    int warp = threadIdx.x >> 5;
    int lane = threadIdx.x & 31;
    int t = blockIdx.x * 8 + warp;
    float4 v = ((const float4*)(x + (size_t)t * CCH))[lane];
    float s  = v.x + v.y + v.z + v.w;
    float sq = v.x*v.x + v.y*v.y + v.z*v.z + v.w*v.w;
    #pragma unroll
    for (int o = 16; o; o >>= 1) {
        s  += __shfl_xor_sync(0xffffffffu, s,  o);
        sq += __shfl_xor_sync(0xffffffffu, sq, o);
    }
    float mean = s * (1.0f / CCH);
    float var  = sq * (1.0f / CCH) - mean * mean;
    float rstd = rsqrtf(var + EPSV);
    float4 gv = ((const float4*)g)[lane];
    float4 bv = ((const float4*)b)[lane];
    float rx = (v.x - mean) * rstd * gv.x + bv.x;
    float ry = (v.y - mean) * rstd * gv.y + bv.y;
    float rz = (v.z - mean) * rstd * gv.z + bv.z;
    float rw = (v.w - mean) * rstd * gv.w + bv.w;
    size_t ot;
    if (PERM) {
        int bi = t >> 16;
        int oh = (t >> 8) & 255;
        int ow = t & 255;
        int sh = (oh + 252) & 255;
        int sw = (ow + 252) & 255;
        int wh = sh >> 3, ii = sh & 7;
        int wc = sw >> 3, jj = sw & 7;
        int win = (bi * 32 + wh) * 32 + wc;
        ot = (size_t)win * 64 + ii * 8 + jj;
    } else {
        ot = (size_t)t;
    }
    uint2 pk;
    pk.x = pack_bf16(rx, ry);
    pk.y = pack_bf16(rz, rw);
    *(uint2*)(out + ot * CCH + lane * 4) = pk;
}

// ---------------- HMMA bf16 GEMM: BM=128 BN=128 BK=32, 256 thr, double-buffered
// A: bf16 [M,K] row-major. Bw: bf16 [K,N] row-major. N also = C row stride for EPI 0/2.
// EPI: 0 = bias -> bf16 C ; 1 = bias + window-reverse + x residual -> fp32 C (stride 128)
//      2 = bias + GELU -> bf16 C ; 3 = bias + residual(extra) -> fp32 C (stride 128)
template<int EPI, int K, int N>
__global__ __launch_bounds__(256) void tgemm(
    const __nv_bfloat16* __restrict__ A, const __nv_bfloat16* __restrict__ Bw,
    const float* __restrict__ bias, const float* __restrict__ extra, void* __restrict__ Cout)
{
    __shared__ __align__(128) __nv_bfloat16 As[2][128 * 32];   // 8KB each
    __shared__ __align__(128) __nv_bfloat16 Bs[2][32 * 128];   // 8KB each

    const int tid  = threadIdx.x;
    const int lane = tid & 31;
    const int wid  = tid >> 5;
    const int wm   = wid & 3;     // 4 m-warps: 32 rows each
    const int wn   = wid >> 2;    // 2 n-warps: 64 cols each
    const int bm   = blockIdx.y * 128;
    const int bn   = blockIdx.x * 128;

    const uint32_t s_a0 = smem_u32(As[0]);
    const uint32_t s_b0 = smem_u32(Bs[0]);

    const int NCH = K / 32;

    // A phys: row(0..127)*64B + (seg ^ ((row>>1)&3))*16  (seg 0..3)
    // B phys: row(0..31)*256B + (seg ^ (row&7))*16        (seg 0..15)
    auto load_chunk = [&](int c, int buf) {
        uint32_t abase = s_a0 + buf * 8192;
        #pragma unroll
        for (int r = 0; r < 2; r++) {
            int s = tid + r * 256;         // 0..511
            int row = s >> 2, seg = s & 3;
            cp_async16(abase + row * 64 + ((seg ^ ((row >> 1) & 3)) << 4),
                       A + (size_t)(bm + row) * K + c * 32 + seg * 8);
        }
        uint32_t bbase = s_b0 + buf * 8192;
        #pragma unroll
        for (int r = 0; r < 2; r++) {
            int s = tid + r * 256;         // 0..511
            int row = s >> 4, seg = s & 15;
            cp_async16(bbase + row * 256 + ((seg ^ (row & 7)) << 4),
                       Bw + (size_t)(c * 32 + row) * N + bn + seg * 8);
        }
    };

    float d[2][8][4];
    #pragma unroll
    for (int mi = 0; mi < 2; mi++)
        #pragma unroll
        for (int ni = 0; ni < 8; ni++)
            #pragma unroll
            for (int r = 0; r < 4; r++) d[mi][ni][r] = 0.0f;

    load_chunk(0, 0);
    cp_commit();

    const int lrow = lane & 15;
    const int lseg = lane >> 4;

    for (int c = 0; c < NCH; c++) {
        int buf = c & 1;
        if (c + 1 < NCH) {
            load_chunk(c + 1, buf ^ 1);
            cp_commit();
            cp_wait<1>();
        } else {
            cp_wait<0>();
        }
        __syncthreads();

        uint32_t abase = s_a0 + buf * 8192;
        uint32_t bbase = s_b0 + buf * 8192;
        #pragma unroll
        for (int ks = 0; ks < 2; ks++) {
            uint32_t a[2][4];
            #pragma unroll
            for (int mi = 0; mi < 2; mi++) {
                int row = wm * 32 + mi * 16 + lrow;
                int seg = ks * 2 + lseg;
                ldm_x4(a[mi], abase + row * 64 + ((seg ^ ((row >> 1) & 3)) << 4));
            }
            uint32_t b[4][4];
            #pragma unroll
            for (int bp = 0; bp < 4; bp++) {
                int row = ks * 16 + lrow;
                int seg = wn * 8 + bp * 2 + lseg;
                ldm_x4_t(b[bp], bbase + row * 256 + ((seg ^ (row & 7)) << 4));
            }
            #pragma unroll
            for (int mi = 0; mi < 2; mi++)
                #pragma unroll
                for (int ni = 0; ni < 8; ni++)
                    mma16816(d[mi][ni], a[mi], b[ni >> 1][(ni & 1) * 2], b[ni >> 1][(ni & 1) * 2 + 1]);
        }
        __syncthreads();
    }

    // ---------------- epilogue ----------------
    const int l4 = lane >> 2, lm = lane & 3;
    float2 bs[8];
    #pragma unroll
    for (int ni = 0; ni < 8; ni++)
        bs[ni] = *(const float2*)(bias + bn + wn * 64 + ni * 8 + lm * 2);

    #pragma unroll
    for (int mi = 0; mi < 2; mi++) {
        #pragma unroll
        for (int half = 0; half < 2; half++) {
            int row = bm + wm * 32 + mi * 16 + half * 8 + l4;
            if (EPI == 0 || EPI == 2) {
                __nv_bfloat16* C = (__nv_bfloat16*)Cout;
                #pragma unroll
                for (int ni = 0; ni < 8; ni++) {
                    int col = bn + wn * 64 + ni * 8 + lm * 2;
                    float v0 = d[mi][ni][half * 2 + 0] + bs[ni].x;
                    float v1 = d[mi][ni][half * 2 + 1] + bs[ni].y;
                    if (EPI == 2) { v0 = gelu_exact(v0); v1 = gelu_exact(v1); }
                    *(uint32_t*)(C + (size_t)row * N + col) = pack_bf16(v0, v1);
                }
            } else if (EPI == 1) {
                float* C = (float*)Cout;
                int win = row >> 6, r6 = row & 63;
                int bi = win >> 10, wim = win & 1023;
                int wh = wim >> 5, wc = wim & 31;
                int ii = r6 >> 3, jj = r6 & 7;
                int oh = (wh * 8 + ii + 4) & 255;
                int ow = (wc * 8 + jj + 4) & 255;
                size_t orow = ((size_t)(bi * 256 + oh) * 256 + ow);
                #pragma unroll
                for (int ni = 0; ni < 8; ni++) {
                    int col = bn + wn * 64 + ni * 8 + lm * 2;
                    float2 xr = *(const float2*)(extra + orow * 128 + col);
                    float2 v;
                    v.x = d[mi][ni][half * 2 + 0] + bs[ni].x + xr.x;
                    v.y = d[mi][ni][half * 2 + 1] + bs[ni].y + xr.y;
                    *(float2*)(C + orow * 128 + col) = v;
                }
            } else { // EPI == 3
                float* C = (float*)Cout;
                #pragma unroll
                for (int ni = 0; ni < 8; ni++) {
                    int col = bn + wn * 64 + ni * 8 + lm * 2;
                    float2 res = *(const float2*)(extra + (size_t)row * 128 + col);
                    float2 v;
                    v.x = d[mi][ni][half * 2 + 0] + bs[ni].x + res.x;
                    v.y = d[mi][ni][half * 2 + 1] + bs[ni].y + res.y;
                    *(float2*)(C + (size_t)row * 128 + col) = v;
                }
            }
        }
    }
}

// ---------------- windowed attention via mma: one block per window -------------
// 256 threads = 8 warps; warp w -> head h = w>>1, row-half = w&1 (32 rows).
// QK^T and P@V on tensor cores; softmax in registers (quad shuffles).
// dynamic shared: q/k/v tiles [64][136] bf16 (pitch 272B) + rpb table + labels.
#define ATT_PITCH 272
#define ATT_QOFF  0
#define ATT_KOFF  17408
#define ATT_VOFF  34816
#define ATT_TOFF  52224
#define ATT_LOFF  55824
#define ATT_SMEM  56080

__global__ __launch_bounds__(256) void attn_mma(const __nv_bfloat16* __restrict__ qkv,
                                                const float* __restrict__ rpb,
                                                __nv_bfloat16* __restrict__ out) {
    extern __shared__ char sm[];
    float* tbl = (float*)(sm + ATT_TOFF);
    int*   lab = (int*)(sm + ATT_LOFF);

    int win  = blockIdx.x;
    int tid  = threadIdx.x;
    int lane = tid & 31, wid = tid >> 5;
    int h    = wid >> 1, half = wid & 1;
    int l4   = lane >> 2, lm = lane & 3;

    uint32_t s_base = smem_u32(sm);
    uint32_t s_q = s_base + ATT_QOFF, s_k = s_base + ATT_KOFF, s_v = s_base + ATT_VOFF;

    // async load q/k/v: 64 tokens x 3 x 16 chunks(16B)
    const __nv_bfloat16* src = qkv + (size_t)win * 64 * 384;
    for (int p = tid; p < 64 * 48; p += 256) {
        int tok = p / 48, c = p % 48;
        int which = c >> 4, seg = c & 15;
        uint32_t dst = (which == 0 ? s_q : (which == 1 ? s_k : s_v)) + tok * ATT_PITCH + seg * 16;
        cp_async16(dst, src + tok * 384 + which * 128 + seg * 8);
    }
    cp_commit();
    for (int p = tid; p < 900; p += 256) tbl[p] = rpb[p];
    if (tid < 64) {
        int wim = win & 1023;
        int wh = wim >> 5, wc = wim & 31;
        int r = wh * 8 + (tid >> 3);
        int c = wc * 8 + (tid & 7);
        int rr = (r < 248) ? 0 : ((r < 252) ? 1 : 2);
        int rc = (c < 248) ? 0 : ((c < 252) ? 1 : 2);
        lab[tid] = rr * 3 + rc;
    }
    cp_wait<0>();
    __syncthreads();

    const int lrow = lane & 15, lseg = lane >> 4;
    const int mbase = half * 32;

    // ---- S = Q K^T  (rows mbase..mbase+31, cols 0..63, d=32) ----
    float S[2][8][4];
    #pragma unroll
    for (int mi = 0; mi < 2; mi++)
        #pragma unroll
        for (int ni = 0; ni < 8; ni++)
            #pragma unroll
            for (int r = 0; r < 4; r++) S[mi][ni][r] = 0.0f;

    #pragma unroll
    for (int ks = 0; ks < 2; ks++) {
        uint32_t a[2][4], b[4][4];
        #pragma unroll
        for (int mi = 0; mi < 2; mi++) {
            int row = mbase + mi * 16 + lrow;
            ldm_x4(a[mi], s_q + row * ATT_PITCH + h * 64 + (ks * 2 + lseg) * 16);
        }
        #pragma unroll
        for (int nt = 0; nt < 4; nt++) {
            int row = nt * 16 + lrow;
            ldm_x4(b[nt], s_k + row * ATT_PITCH + h * 64 + (ks * 2 + lseg) * 16);
        }
        // n-tile ni: even -> {r0, r2}, odd -> {r1, r3} of b[ni>>1]
        #pragma unroll
        for (int mi = 0; mi < 2; mi++)
            #pragma unroll
            for (int ni = 0; ni < 8; ni++)
                mma16816(S[mi][ni], a[mi], b[ni >> 1][ni & 1], b[ni >> 1][(ni & 1) + 2]);
    }

    // ---- scale + rel-pos bias + shift mask, softmax over rows ----
    const float scale = 0.17677669529663687f;
    float mx[2][2], sum[2][2];
    #pragma unroll
    for (int mi = 0; mi < 2; mi++) {
        #pragma unroll
        for (int rr = 0; rr < 2; rr++) {
            int i = mbase + mi * 16 + rr * 8 + l4;
            int ih = i >> 3, iw = i & 7;
            int li = lab[i];
            float m = -1e30f;
            #pragma unroll
            for (int ni = 0; ni < 8; ni++) {
                #pragma unroll
                for (int e = 0; e < 2; e++) {
                    int j = ni * 8 + lm * 2 + e;
                    int jh = j >> 3, jw = j & 7;
                    float v = S[mi][ni][rr * 2 + e] * scale
                            + tbl[((ih - jh + 7) * 15 + (iw - jw + 7)) * 4 + h];
                    if (lab[j] != li) v -= 100.0f;
                    S[mi][ni][rr * 2 + e] = v;
                    m = fmaxf(m, v);
                }
            }
            m = fmaxf(m, __shfl_xor_sync(0xffffffffu, m, 1));
            m = fmaxf(m, __shfl_xor_sync(0xffffffffu, m, 2));
            float sm_ = 0.0f;
            #pragma unroll
            for (int ni = 0; ni < 8; ni++) {
                #pragma unroll
                for (int e = 0; e < 2; e++) {
                    float ev = __expf(S[mi][ni][rr * 2 + e] - m);
                    S[mi][ni][rr * 2 + e] = ev;
                    sm_ += ev;
                }
            }
            sm_ += __shfl_xor_sync(0xffffffffu, sm_, 1);
            sm_ += __shfl_xor_sync(0xffffffffu, sm_, 2);
            mx[mi][rr] = m;
            sum[mi][rr] = sm_;
        }
    }

    // ---- pack P to bf16 A-fragments (C-frag layout == A-frag layout) ----
    uint32_t P[2][8][2];
    #pragma unroll
    for (int mi = 0; mi < 2; mi++)
        #pragma unroll
        for (int ni = 0; ni < 8; ni++) {
            P[mi][ni][0] = pack_bf16(S[mi][ni][0], S[mi][ni][1]);
            P[mi][ni][1] = pack_bf16(S[mi][ni][2], S[mi][ni][3]);
        }

    // ---- O = P V ----
    float o[2][4][4];
    #pragma unroll
    for (int mi = 0; mi < 2; mi++)
        #pragma unroll
        for (int nd = 0; nd < 4; nd++)
            #pragma unroll
            for (int r = 0; r < 4; r++) o[mi][nd][r] = 0.0f;

    #pragma unroll
    for (int kn = 0; kn < 4; kn++) {       // k = token dim, 4 x 16
        uint32_t vb[2][4];
        #pragma unroll
        for (int vp = 0; vp < 2; vp++) {
            int row = kn * 16 + lrow;
            ldm_x4_t(vb[vp], s_v + row * ATT_PITCH + h * 64 + (vp * 2 + lseg) * 16);
        }
        #pragma unroll
        for (int mi = 0; mi < 2; mi++) {
            uint32_t a[4] = { P[mi][2 * kn][0], P[mi][2 * kn][1],
                              P[mi][2 * kn + 1][0], P[mi][2 * kn + 1][1] };
            #pragma unroll
            for (int nd = 0; nd < 4; nd++)
                mma16816(o[mi][nd], a, vb[nd >> 1][(nd & 1) * 2], vb[nd >> 1][(nd & 1) * 2 + 1]);
        }
    }

    // ---- normalize + store ----
    #pragma unroll
    for (int mi = 0; mi < 2; mi++) {
        #pragma unroll
        for (int rr = 0; rr < 2; rr++) {
            float inv = 1.0f / sum[mi][rr];
            size_t row = (size_t)win * 64 + mbase + mi * 16 + rr * 8 + l4;
            #pragma unroll
            for (int nd = 0; nd < 4; nd++) {
                int col = h * 32 + nd * 8 + lm * 2;
                *(uint32_t*)(out + row * 128 + col) =
                    pack_bf16(o[mi][nd][rr * 2] * inv, o[mi][nd][rr * 2 + 1] * inv);
            }
        }
    }
}

// ---------------- launch ----------------
extern "C" void kernel_launch(void* const* d_in, const int* in_sizes, int n_in,
                              void* d_out, int out_size) {
    const float* x      = (const float*)d_in[0];
    const float* gamma1 = (const float*)d_in[1];
    const float* beta1  = (const float*)d_in[2];
    const float* qkv_w  = (const float*)d_in[3];
    const float* qkv_b  = (const float*)d_in[4];
    const float* proj_w = (const float*)d_in[5];
    const float* proj_b = (const float*)d_in[6];
    const float* rpb    = (const float*)d_in[7];
    const float* gamma2 = (const float*)d_in[8];
    const float* beta2  = (const float*)d_in[9];
    const float* w1     = (const float*)d_in[10];
    const float* b1     = (const float*)d_in[11];
    const float* w2     = (const float*)d_in[12];
    const float* b2     = (const float*)d_in[13];
    float* out = (float*)d_out;

    __nv_bfloat16 *xw, *qkv, *att, *h2, *m1, *wq, *wp, *w1b, *w2b;
    float *y1;
    cudaGetSymbolAddress((void**)&xw,  g_xw);
    cudaGetSymbolAddress((void**)&qkv, g_qkv);
    cudaGetSymbolAddress((void**)&att, g_att);
    cudaGetSymbolAddress((void**)&y1,  g_y1);
    cudaGetSymbolAddress((void**)&h2,  g_h2);
    cudaGetSymbolAddress((void**)&m1,  g_m1);
    cudaGetSymbolAddress((void**)&wq,  g_wq);
    cudaGetSymbolAddress((void**)&wp,  g_wp);
    cudaGetSymbolAddress((void**)&w1b, g_w1b);
    cudaGetSymbolAddress((void**)&w2b, g_w2b);

    cudaFuncSetAttribute(attn_mma, cudaFuncAttributeMaxDynamicSharedMemorySize, ATT_SMEM);

    // bf16 weight conversion (one launch, layouts preserved)
    convw_kernel<<<49152 / 256, 256>>>(qkv_w, wq, proj_w, wp, w1, w1b, w2, w2b);

    // 1. LN1 + shift + window partition (bf16)
    ln_kernel<1><<<TOK / 8, 256>>>(x, gamma1, beta1, xw);
    // 2. qkv GEMM  [T,128]@[128,384] -> bf16
    tgemm<0, 128, 384><<<dim3(3, TOK / 128), 256>>>(xw, wq, qkv_b, nullptr, qkv);
    // 3. window attention (tensor cores)
    attn_mma<<<4096, 256, ATT_SMEM>>>(qkv, rpb, att);
    // 4. proj GEMM + window reverse + residual -> y1 fp32 (image layout)
    tgemm<1, 128, 128><<<dim3(1, TOK / 128), 256>>>(att, wp, proj_b, x, y1);
    // 5. LN2 -> bf16
    ln_kernel<0><<<TOK / 8, 256>>>(y1, gamma2, beta2, h2);
    // 6. fc1 + GELU  [T,128]@[128,512] -> bf16
    tgemm<2, 128, 512><<<dim3(4, TOK / 128), 256>>>(h2, w1b, b1, nullptr, m1);
    // 7. fc2 + residual  [T,512]@[512,128] -> fp32 out
    tgemm<3, 512, 128><<<dim3(1, TOK / 128), 256>>>(m1, w2b, b2, y1, out);
}

// round 6
// speedup vs baseline: 4.3076x; 1.0140x over previous
#include <cuda_runtime.h>
#include <cuda_bf16.h>
#include <math.h>
#include <cstdint>

#define BATCH 4
#define HIMG 256
#define WIMG 256
#define CCH 128
#define TOK (BATCH*HIMG*WIMG)   // 262144
#define EPSV 1.001e-05f

// ---------------- scratch (static device arrays; no allocation) ----------------
__device__ __align__(16) __nv_bfloat16 g_xw [ (size_t)TOK*CCH   ];
__device__ __align__(16) __nv_bfloat16 g_qkv[ (size_t)TOK*3*CCH ];
__device__ __align__(16) __nv_bfloat16 g_att[ (size_t)TOK*CCH   ];
__device__ __align__(16) float         g_y1 [ (size_t)TOK*CCH   ];
__device__ __align__(16) __nv_bfloat16 g_h2 [ (size_t)TOK*CCH   ];
__device__ __align__(16) __nv_bfloat16 g_m1 [ (size_t)TOK*4*CCH ];
// bf16 weights, same [K][N] row-major layout as the fp32 originals
__device__ __align__(16) __nv_bfloat16 g_wq [ 128*384 ];
__device__ __align__(16) __nv_bfloat16 g_wp [ 128*128 ];
__device__ __align__(16) __nv_bfloat16 g_w1b[ 128*512 ];
__device__ __align__(16) __nv_bfloat16 g_w2b[ 512*128 ];

// ---------------- helpers ----------------
__device__ __forceinline__ uint32_t smem_u32(const void* p) {
    uint32_t a;
    asm("{ .reg .u64 t; cvta.to.shared.u64 t, %1; cvt.u32.u64 %0, t; }" : "=r"(a) : "l"(p));
    return a;
}
__device__ __forceinline__ uint32_t pack_bf16(float lo, float hi) {
    uint32_t r;
    asm("cvt.rn.bf16x2.f32 %0, %1, %2;" : "=r"(r) : "f"(hi), "f"(lo));
    return r;
}
__device__ __forceinline__ void cp_async16(uint32_t dst, const void* src) {
    asm volatile("cp.async.cg.shared.global [%0], [%1], 16;" :: "r"(dst), "l"(src));
}
__device__ __forceinline__ void cp_commit() { asm volatile("cp.async.commit_group;"); }
template<int N>
__device__ __forceinline__ void cp_wait() { asm volatile("cp.async.wait_group %0;" :: "n"(N)); }

__device__ __forceinline__ void ldm_x4(uint32_t* r, uint32_t a) {
    asm volatile("ldmatrix.sync.aligned.m8n8.x4.shared.b16 {%0,%1,%2,%3}, [%4];"
        : "=r"(r[0]), "=r"(r[1]), "=r"(r[2]), "=r"(r[3]) : "r"(a));
}
__device__ __forceinline__ void ldm_x4_t(uint32_t* r, uint32_t a) {
    asm volatile("ldmatrix.sync.aligned.m8n8.x4.trans.shared.b16 {%0,%1,%2,%3}, [%4];"
        : "=r"(r[0]), "=r"(r[1]), "=r"(r[2]), "=r"(r[3]) : "r"(a));
}
__device__ __forceinline__ void mma16816(float* d, const uint32_t* a, uint32_t b0, uint32_t b1) {
    asm volatile("mma.sync.aligned.m16n8k16.row.col.f32.bf16.bf16.f32 "
        "{%0,%1,%2,%3}, {%4,%5,%6,%7}, {%8,%9}, {%0,%1,%2,%3};"
        : "+f"(d[0]), "+f"(d[1]), "+f"(d[2]), "+f"(d[3])
        : "r"(a[0]), "r"(a[1]), "r"(a[2]), "r"(a[3]), "r"(b0), "r"(b1));
}
__device__ __forceinline__ float gelu_exact(float x) {
    return 0.5f * x * (1.0f + erff(x * 0.70710678118654752f));
}

// ---------------- fp32 -> bf16 weight convert, all 4 weights in one launch -----
__global__ void convw_kernel(const float* __restrict__ w0, __nv_bfloat16* __restrict__ t0,
                             const float* __restrict__ w1, __nv_bfloat16* __restrict__ t1,
                             const float* __restrict__ w2, __nv_bfloat16* __restrict__ t2,
                             const float* __restrict__ w3, __nv_bfloat16* __restrict__ t3) {
    int i = blockIdx.x * 256 + threadIdx.x;
    const float* w; __nv_bfloat16* t; int base;
    if (i < 12288)      { w = w0; t = t0; base = 0; }
    else if (i < 16384) { w = w1; t = t1; base = 12288; }
    else if (i < 32768) { w = w2; t = t2; base = 16384; }
    else                { w = w3; t = t3; base = 32768; }
    int j = i - base;
    float4 v = ((const float4*)w)[j];
    uint2 p;
    p.x = pack_bf16(v.x, v.y);
    p.y = pack_bf16(v.z, v.w);
    *(uint2*)(t + (size_t)j * 4) = p;
}

// ---------------- LayerNorm (one warp per token) + window permute --------------
template<int PERM>
__global__ void ln_kernel(const float* __restrict__ x, const float* __restrict__ g,
                          const float* __restrict__ b, __nv_bfloat16* __restrict__ out) {
    int warp = threadIdx.x >> 5;
    int lane = threadIdx.x & 31;
    int t = blockIdx.x * 8 + warp;
    float4 v = ((const float4*)(x + (size_t)t * CCH))[lane];
    float s  = v.x + v.y + v.z + v.w;
    float sq = v.x*v.x + v.y*v.y + v.z*v.z + v.w*v.w;
    #pragma unroll
    for (int o = 16; o; o >>= 1) {
        s  += __shfl_xor_sync(0xffffffffu, s,  o);
        sq += __shfl_xor_sync(0xffffffffu, sq, o);
    }
    float mean = s * (1.0f / CCH);
    float var  = sq * (1.0f / CCH) - mean * mean;
    float rstd = rsqrtf(var + EPSV);
    float4 gv = ((const float4*)g)[lane];
    float4 bv = ((const float4*)b)[lane];
    float rx = (v.x - mean) * rstd * gv.x + bv.x;
    float ry = (v.y - mean) * rstd * gv.y + bv.y;
    float rz = (v.z - mean) * rstd * gv.z + bv.z;
    float rw = (v.w - mean) * rstd * gv.w + bv.w;
    size_t ot;
    if (PERM) {
        int bi = t >> 16;
        int oh = (t >> 8) & 255;
        int ow = t & 255;
        int sh = (oh + 252) & 255;
        int sw = (ow + 252) & 255;
        int wh = sh >> 3, ii = sh & 7;
        int wc = sw >> 3, jj = sw & 7;
        int win = (bi * 32 + wh) * 32 + wc;
        ot = (size_t)win * 64 + ii * 8 + jj;
    } else {
        ot = (size_t)t;
    }
    uint2 pk;
    pk.x = pack_bf16(rx, ry);
    pk.y = pack_bf16(rz, rw);
    *(uint2*)(out + ot * CCH + lane * 4) = pk;
}

// ---------------- HMMA bf16 GEMM: BM=128 BN=128 BK=32, 256 thr, double-buffered
// EPI: 0 = bias -> bf16 C
//      1 = bias + window-reverse + x residual -> fp32 C (stride 128) + fused LN2 -> h2 bf16
//      2 = bias + GELU -> bf16 C
//      3 = bias + residual(extra) -> fp32 C (stride 128)
template<int EPI, int K, int N>
__global__ __launch_bounds__(256) void tgemm(
    const __nv_bfloat16* __restrict__ A, const __nv_bfloat16* __restrict__ Bw,
    const float* __restrict__ bias, const float* __restrict__ extra, void* __restrict__ Cout,
    const float* __restrict__ g2, const float* __restrict__ b2, __nv_bfloat16* __restrict__ h2out)
{
    __shared__ __align__(128) __nv_bfloat16 As[2][128 * 32];   // 8KB each
    __shared__ __align__(128) __nv_bfloat16 Bs[2][32 * 128];   // 8KB each
    __shared__ float2 lnstat[128][2];                          // 2KB (EPI 1 only)

    const int tid  = threadIdx.x;
    const int lane = tid & 31;
    const int wid  = tid >> 5;
    const int wm   = wid & 3;     // 4 m-warps: 32 rows each
    const int wn   = wid >> 2;    // 2 n-warps: 64 cols each
    const int bm   = blockIdx.y * 128;
    const int bn   = blockIdx.x * 128;

    const uint32_t s_a0 = smem_u32(As[0]);
    const uint32_t s_b0 = smem_u32(Bs[0]);

    const int NCH = K / 32;

    auto load_chunk = [&](int c, int buf) {
        uint32_t abase = s_a0 + buf * 8192;
        #pragma unroll
        for (int r = 0; r < 2; r++) {
            int s = tid + r * 256;
            int row = s >> 2, seg = s & 3;
            cp_async16(abase + row * 64 + ((seg ^ ((row >> 1) & 3)) << 4),
                       A + (size_t)(bm + row) * K + c * 32 + seg * 8);
        }
        uint32_t bbase = s_b0 + buf * 8192;
        #pragma unroll
        for (int r = 0; r < 2; r++) {
            int s = tid + r * 256;
            int row = s >> 4, seg = s & 15;
            cp_async16(bbase + row * 256 + ((seg ^ (row & 7)) << 4),
                       Bw + (size_t)(c * 32 + row) * N + bn + seg * 8);
        }
    };

    float d[2][8][4];
    #pragma unroll
    for (int mi = 0; mi < 2; mi++)
        #pragma unroll
        for (int ni = 0; ni < 8; ni++)
            #pragma unroll
            for (int r = 0; r < 4; r++) d[mi][ni][r] = 0.0f;

    load_chunk(0, 0);
    cp_commit();

    const int lrow = lane & 15;
    const int lseg = lane >> 4;

    for (int c = 0; c < NCH; c++) {
        int buf = c & 1;
        if (c + 1 < NCH) {
            load_chunk(c + 1, buf ^ 1);
            cp_commit();
            cp_wait<1>();
        } else {
            cp_wait<0>();
        }
        __syncthreads();

        uint32_t abase = s_a0 + buf * 8192;
        uint32_t bbase = s_b0 + buf * 8192;
        #pragma unroll
        for (int ks = 0; ks < 2; ks++) {
            uint32_t a[2][4];
            #pragma unroll
            for (int mi = 0; mi < 2; mi++) {
                int row = wm * 32 + mi * 16 + lrow;
                int seg = ks * 2 + lseg;
                ldm_x4(a[mi], abase + row * 64 + ((seg ^ ((row >> 1) & 3)) << 4));
            }
            uint32_t b[4][4];
            #pragma unroll
            for (int bp = 0; bp < 4; bp++) {
                int row = ks * 16 + lrow;
                int seg = wn * 8 + bp * 2 + lseg;
                ldm_x4_t(b[bp], bbase + row * 256 + ((seg ^ (row & 7)) << 4));
            }
            #pragma unroll
            for (int mi = 0; mi < 2; mi++)
                #pragma unroll
                for (int ni = 0; ni < 8; ni++)
                    mma16816(d[mi][ni], a[mi], b[ni >> 1][(ni & 1) * 2], b[ni >> 1][(ni & 1) * 2 + 1]);
        }
        __syncthreads();
    }

    // ---------------- epilogue ----------------
    const int l4 = lane >> 2, lm = lane & 3;
    float2 bs[8];
    #pragma unroll
    for (int ni = 0; ni < 8; ni++)
        bs[ni] = *(const float2*)(bias + bn + wn * 64 + ni * 8 + lm * 2);

    if (EPI == 0 || EPI == 2) {
        #pragma unroll
        for (int mi = 0; mi < 2; mi++) {
            #pragma unroll
            for (int half = 0; half < 2; half++) {
                int row = bm + wm * 32 + mi * 16 + half * 8 + l4;
                __nv_bfloat16* C = (__nv_bfloat16*)Cout;
                #pragma unroll
                for (int ni = 0; ni < 8; ni++) {
                    int col = bn + wn * 64 + ni * 8 + lm * 2;
                    float v0 = d[mi][ni][half * 2 + 0] + bs[ni].x;
                    float v1 = d[mi][ni][half * 2 + 1] + bs[ni].y;
                    if (EPI == 2) { v0 = gelu_exact(v0); v1 = gelu_exact(v1); }
                    *(uint32_t*)(C + (size_t)row * N + col) = pack_bf16(v0, v1);
                }
            }
        }
    } else if (EPI == 1) {
        // proj: residual + window reverse scatter to y1 fp32, then fused LN2 -> h2 bf16
        float* C = (float*)Cout;
        size_t orows[2][2];
        #pragma unroll
        for (int mi = 0; mi < 2; mi++) {
            #pragma unroll
            for (int half = 0; half < 2; half++) {
                int row = bm + wm * 32 + mi * 16 + half * 8 + l4;
                int win = row >> 6, r6 = row & 63;
                int bi = win >> 10, wim = win & 1023;
                int wh = wim >> 5, wc = wim & 31;
                int ii = r6 >> 3, jj = r6 & 7;
                int oh = (wh * 8 + ii + 4) & 255;
                int ow = (wc * 8 + jj + 4) & 255;
                size_t orow = ((size_t)(bi * 256 + oh) * 256 + ow);
                orows[mi][half] = orow;
                float s = 0.0f, sq = 0.0f;
                #pragma unroll
                for (int ni = 0; ni < 8; ni++) {
                    int col = wn * 64 + ni * 8 + lm * 2;
                    float2 xr = *(const float2*)(extra + orow * 128 + col);
                    float v0 = d[mi][ni][half * 2 + 0] + bs[ni].x + xr.x;
                    float v1 = d[mi][ni][half * 2 + 1] + bs[ni].y + xr.y;
                    d[mi][ni][half * 2 + 0] = v0;
                    d[mi][ni][half * 2 + 1] = v1;
                    s  += v0 + v1;
                    sq += v0 * v0 + v1 * v1;
                    float2 v; v.x = v0; v.y = v1;
                    *(float2*)(C + orow * 128 + col) = v;
                }
                s  += __shfl_xor_sync(0xffffffffu, s,  1);
                sq += __shfl_xor_sync(0xffffffffu, sq, 1);
                s  += __shfl_xor_sync(0xffffffffu, s,  2);
                sq += __shfl_xor_sync(0xffffffffu, sq, 2);
                if (lm == 0) {
                    float2 st; st.x = s; st.y = sq;
                    lnstat[row - bm][wn] = st;
                }
            }
        }
        __syncthreads();
        float2 g2v[8], b2v[8];
        #pragma unroll
        for (int ni = 0; ni < 8; ni++) {
            g2v[ni] = *(const float2*)(g2 + wn * 64 + ni * 8 + lm * 2);
            b2v[ni] = *(const float2*)(b2 + wn * 64 + ni * 8 + lm * 2);
        }
        #pragma unroll
        for (int mi = 0; mi < 2; mi++) {
            #pragma unroll
            for (int half = 0; half < 2; half++) {
                int rl = wm * 32 + mi * 16 + half * 8 + l4;
                float2 sa = lnstat[rl][0], sb = lnstat[rl][1];
                float mean = (sa.x + sb.x) * (1.0f / CCH);
                float var  = (sa.y + sb.y) * (1.0f / CCH) - mean * mean;
                float rstd = rsqrtf(var + EPSV);
                size_t orow = orows[mi][half];
                #pragma unroll
                for (int ni = 0; ni < 8; ni++) {
                    int col = wn * 64 + ni * 8 + lm * 2;
                    float h0 = (d[mi][ni][half * 2 + 0] - mean) * rstd * g2v[ni].x + b2v[ni].x;
                    float h1 = (d[mi][ni][half * 2 + 1] - mean) * rstd * g2v[ni].y + b2v[ni].y;
                    *(uint32_t*)(h2out + orow * 128 + col) = pack_bf16(h0, h1);
                }
            }
        }
    } else { // EPI == 3
        float* C = (float*)Cout;
        #pragma unroll
        for (int mi = 0; mi < 2; mi++) {
            #pragma unroll
            for (int half = 0; half < 2; half++) {
                int row = bm + wm * 32 + mi * 16 + half * 8 + l4;
                #pragma unroll
                for (int ni = 0; ni < 8; ni++) {
                    int col = bn + wn * 64 + ni * 8 + lm * 2;
                    float2 res = *(const float2*)(extra + (size_t)row * 128 + col);
                    float2 v;
                    v.x = d[mi][ni][half * 2 + 0] + bs[ni].x + res.x;
                    v.y = d[mi][ni][half * 2 + 1] + bs[ni].y + res.y;
                    *(float2*)(C + (size_t)row * 128 + col) = v;
                }
            }
        }
    }
}

// ---------------- windowed attention via mma: one block per window -------------
#define ATT_PITCH 272
#define ATT_QOFF  0
#define ATT_KOFF  17408
#define ATT_VOFF  34816
#define ATT_TOFF  52224
#define ATT_LOFF  55824
#define ATT_JOFF  56080
#define ATT_SMEM  56336

__global__ __launch_bounds__(256) void attn_mma(const __nv_bfloat16* __restrict__ qkv,
                                                const float* __restrict__ rpb,
                                                __nv_bfloat16* __restrict__ out) {
    extern __shared__ char sm[];
    float* tbl  = (float*)(sm + ATT_TOFF);
    int*   lab  = (int*)(sm + ATT_LOFF);
    int*   joff = (int*)(sm + ATT_JOFF);

    int win  = blockIdx.x;
    int tid  = threadIdx.x;
    int lane = tid & 31, wid = tid >> 5;
    int h    = wid >> 1, half = wid & 1;
    int l4   = lane >> 2, lm = lane & 3;

    uint32_t s_base = smem_u32(sm);
    uint32_t s_q = s_base + ATT_QOFF, s_k = s_base + ATT_KOFF, s_v = s_base + ATT_VOFF;

    int wim = win & 1023;
    int wwh = wim >> 5, wwc = wim & 31;
    bool masked = (wwh == 31) || (wwc == 31);

    // async load q/k/v: 64 tokens x 4 threads; 12 x 16B chunks per thread
    {
        int tok = tid >> 2;
        int s4  = (tid & 3) * 4;
        const __nv_bfloat16* tsrc = qkv + ((size_t)win * 64 + tok) * 384;
        uint32_t dq = s_q + tok * ATT_PITCH;
        uint32_t dk = s_k + tok * ATT_PITCH;
        uint32_t dv = s_v + tok * ATT_PITCH;
        #pragma unroll
        for (int u = 0; u < 4; u++) {
            int seg = s4 + u;
            cp_async16(dq + seg * 16, tsrc + seg * 8);
            cp_async16(dk + seg * 16, tsrc + 128 + seg * 8);
            cp_async16(dv + seg * 16, tsrc + 256 + seg * 8);
        }
    }
    cp_commit();
    for (int p = tid; p < 900; p += 256) tbl[p] = rpb[p];
    if (tid < 64) {
        joff[tid] = (-(tid >> 3) * 15 - (tid & 7)) * 4;
        int r = wwh * 8 + (tid >> 3);
        int c = wwc * 8 + (tid & 7);
        int rr = (r < 248) ? 0 : ((r < 252) ? 1 : 2);
        int rc = (c < 248) ? 0 : ((c < 252) ? 1 : 2);
        lab[tid] = rr * 3 + rc;
    }
    cp_wait<0>();
    __syncthreads();

    const int lrow = lane & 15, lseg = lane >> 4;
    const int mbase = half * 32;

    // ---- S = Q K^T ----
    float S[2][8][4];
    #pragma unroll
    for (int mi = 0; mi < 2; mi++)
        #pragma unroll
        for (int ni = 0; ni < 8; ni++)
            #pragma unroll
            for (int r = 0; r < 4; r++) S[mi][ni][r] = 0.0f;

    #pragma unroll
    for (int ks = 0; ks < 2; ks++) {
        uint32_t a[2][4], b[4][4];
        #pragma unroll
        for (int mi = 0; mi < 2; mi++) {
            int row = mbase + mi * 16 + lrow;
            ldm_x4(a[mi], s_q + row * ATT_PITCH + h * 64 + (ks * 2 + lseg) * 16);
        }
        #pragma unroll
        for (int nt = 0; nt < 4; nt++) {
            int row = nt * 16 + lrow;
            ldm_x4(b[nt], s_k + row * ATT_PITCH + h * 64 + (ks * 2 + lseg) * 16);
        }
        #pragma unroll
        for (int mi = 0; mi < 2; mi++)
            #pragma unroll
            for (int ni = 0; ni < 8; ni++)
                mma16816(S[mi][ni], a[mi], b[ni >> 1][ni & 1], b[ni >> 1][(ni & 1) + 2]);
    }

    // ---- scale + bias (+ mask on edge windows), softmax ----
    const float scale = 0.17677669529663687f;
    float sum[2][2];
    #pragma unroll
    for (int mi = 0; mi < 2; mi++) {
        #pragma unroll
        for (int rr = 0; rr < 2; rr++) {
            int i = mbase + mi * 16 + rr * 8 + l4;
            int rowbase = (((i >> 3) + 7) * 15 + ((i & 7) + 7)) * 4 + h;
            int li = lab[i];
            float m = -1e30f;
            #pragma unroll
            for (int ni = 0; ni < 8; ni++) {
                int j0 = ni * 8 + lm * 2;
                int idx0 = rowbase + joff[j0];
                float v0 = S[mi][ni][rr * 2 + 0] * scale + tbl[idx0];
                float v1 = S[mi][ni][rr * 2 + 1] * scale + tbl[idx0 - 4];
                if (masked) {
                    if (lab[j0] != li)     v0 -= 100.0f;
                    if (lab[j0 + 1] != li) v1 -= 100.0f;
                }
                S[mi][ni][rr * 2 + 0] = v0;
                S[mi][ni][rr * 2 + 1] = v1;
                m = fmaxf(m, fmaxf(v0, v1));
            }
            m = fmaxf(m, __shfl_xor_sync(0xffffffffu, m, 1));
            m = fmaxf(m, __shfl_xor_sync(0xffffffffu, m, 2));
            float sm_ = 0.0f;
            #pragma unroll
            for (int ni = 0; ni < 8; ni++) {
                #pragma unroll
                for (int e = 0; e < 2; e++) {
                    float ev = __expf(S[mi][ni][rr * 2 + e] - m);
                    S[mi][ni][rr * 2 + e] = ev;
                    sm_ += ev;
                }
            }
            sm_ += __shfl_xor_sync(0xffffffffu, sm_, 1);
            sm_ += __shfl_xor_sync(0xffffffffu, sm_, 2);
            sum[mi][rr] = sm_;
        }
    }

    // ---- P -> bf16 A-fragments ----
    uint32_t P[2][8][2];
    #pragma unroll
    for (int mi = 0; mi < 2; mi++)
        #pragma unroll
        for (int ni = 0; ni < 8; ni++) {
            P[mi][ni][0] = pack_bf16(S[mi][ni][0], S[mi][ni][1]);
            P[mi][ni][1] = pack_bf16(S[mi][ni][2], S[mi][ni][3]);
        }

    // ---- O = P V ----
    float o[2][4][4];
    #pragma unroll
    for (int mi = 0; mi < 2; mi++)
        #pragma unroll
        for (int nd = 0; nd < 4; nd++)
            #pragma unroll
            for (int r = 0; r < 4; r++) o[mi][nd][r] = 0.0f;

    #pragma unroll
    for (int kn = 0; kn < 4; kn++) {
        uint32_t vb[2][4];
        #pragma unroll
        for (int vp = 0; vp < 2; vp++) {
            int row = kn * 16 + lrow;
            ldm_x4_t(vb[vp], s_v + row * ATT_PITCH + h * 64 + (vp * 2 + lseg) * 16);
        }
        #pragma unroll
        for (int mi = 0; mi < 2; mi++) {
            uint32_t a[4] = { P[mi][2 * kn][0], P[mi][2 * kn][1],
                              P[mi][2 * kn + 1][0], P[mi][2 * kn + 1][1] };
            #pragma unroll
            for (int nd = 0; nd < 4; nd++)
                mma16816(o[mi][nd], a, vb[nd >> 1][(nd & 1) * 2], vb[nd >> 1][(nd & 1) * 2 + 1]);
        }
    }

    // ---- normalize + store ----
    #pragma unroll
    for (int mi = 0; mi < 2; mi++) {
        #pragma unroll
        for (int rr = 0; rr < 2; rr++) {
            float inv = 1.0f / sum[mi][rr];
            size_t row = (size_t)win * 64 + mbase + mi * 16 + rr * 8 + l4;
            #pragma unroll
            for (int nd = 0; nd < 4; nd++) {
                int col = h * 32 + nd * 8 + lm * 2;
                *(uint32_t*)(out + row * 128 + col) =
                    pack_bf16(o[mi][nd][rr * 2] * inv, o[mi][nd][rr * 2 + 1] * inv);
            }
        }
    }
}

// ---------------- launch ----------------
extern "C" void kernel_launch(void* const* d_in, const int* in_sizes, int n_in,
                              void* d_out, int out_size) {
    const float* x      = (const float*)d_in[0];
    const float* gamma1 = (const float*)d_in[1];
    const float* beta1  = (const float*)d_in[2];
    const float* qkv_w  = (const float*)d_in[3];
    const float* qkv_b  = (const float*)d_in[4];
    const float* proj_w = (const float*)d_in[5];
    const float* proj_b = (const float*)d_in[6];
    const float* rpb    = (const float*)d_in[7];
    const float* gamma2 = (const float*)d_in[8];
    const float* beta2  = (const float*)d_in[9];
    const float* w1     = (const float*)d_in[10];
    const float* b1     = (const float*)d_in[11];
    const float* w2     = (const float*)d_in[12];
    const float* b2     = (const float*)d_in[13];
    float* out = (float*)d_out;

    __nv_bfloat16 *xw, *qkv, *att, *h2, *m1, *wq, *wp, *w1b, *w2b;
    float *y1;
    cudaGetSymbolAddress((void**)&xw,  g_xw);
    cudaGetSymbolAddress((void**)&qkv, g_qkv);
    cudaGetSymbolAddress((void**)&att, g_att);
    cudaGetSymbolAddress((void**)&y1,  g_y1);
    cudaGetSymbolAddress((void**)&h2,  g_h2);
    cudaGetSymbolAddress((void**)&m1,  g_m1);
    cudaGetSymbolAddress((void**)&wq,  g_wq);
    cudaGetSymbolAddress((void**)&wp,  g_wp);
    cudaGetSymbolAddress((void**)&w1b, g_w1b);
    cudaGetSymbolAddress((void**)&w2b, g_w2b);

    cudaFuncSetAttribute(attn_mma, cudaFuncAttributeMaxDynamicSharedMemorySize, ATT_SMEM);

    // bf16 weight conversion (one launch, layouts preserved)
    convw_kernel<<<49152 / 256, 256>>>(qkv_w, wq, proj_w, wp, w1, w1b, w2, w2b);

    // 1. LN1 + shift + window partition (bf16)
    ln_kernel<1><<<TOK / 8, 256>>>(x, gamma1, beta1, xw);
    // 2. qkv GEMM  [T,128]@[128,384] -> bf16
    tgemm<0, 128, 384><<<dim3(3, TOK / 128), 256>>>(xw, wq, qkv_b, nullptr, qkv, nullptr, nullptr, nullptr);
    // 3. window attention (tensor cores)
    attn_mma<<<4096, 256, ATT_SMEM>>>(qkv, rpb, att);
    // 4. proj GEMM + window reverse + residual -> y1 fp32, fused LN2 -> h2 bf16
    tgemm<1, 128, 128><<<dim3(1, TOK / 128), 256>>>(att, wp, proj_b, x, y1, gamma2, beta2, h2);
    // 5. fc1 + GELU  [T,128]@[128,512] -> bf16
    tgemm<2, 128, 512><<<dim3(4, TOK / 128), 256>>>(h2, w1b, b1, nullptr, m1, nullptr, nullptr, nullptr);
    // 6. fc2 + residual  [T,512]@[512,128] -> fp32 out
    tgemm<3, 512, 128><<<dim3(1, TOK / 128), 256>>>(m1, w2b, b2, y1, out, nullptr, nullptr, nullptr);
}

// round 7
// speedup vs baseline: 4.3838x; 1.0177x over previous
#include <cuda_runtime.h>
#include <cuda_bf16.h>
#include <math.h>
#include <cstdint>

#define BATCH 4
#define HIMG 256
#define WIMG 256
#define CCH 128
#define TOK (BATCH*HIMG*WIMG)   // 262144
#define EPSV 1.001e-05f

// ---------------- scratch (static device arrays; no allocation) ----------------
__device__ __align__(16) __nv_bfloat16 g_xw [ (size_t)TOK*CCH ];
__device__ __align__(16) __nv_bfloat16 g_att[ (size_t)TOK*CCH ];
__device__ __align__(16) float         g_y1 [ (size_t)TOK*CCH ];
__device__ __align__(16) __nv_bfloat16 g_h2 [ (size_t)TOK*CCH ];
// bf16 weights, same [K][N] row-major layout as the fp32 originals
__device__ __align__(16) __nv_bfloat16 g_wq [ 128*384 ];
__device__ __align__(16) __nv_bfloat16 g_wp [ 128*128 ];
__device__ __align__(16) __nv_bfloat16 g_w1b[ 128*512 ];
__device__ __align__(16) __nv_bfloat16 g_w2b[ 512*128 ];

// ---------------- helpers ----------------
__device__ __forceinline__ uint32_t smem_u32(const void* p) {
    uint32_t a;
    asm("{ .reg .u64 t; cvta.to.shared.u64 t, %1; cvt.u32.u64 %0, t; }" : "=r"(a) : "l"(p));
    return a;
}
__device__ __forceinline__ uint32_t pack_bf16(float lo, float hi) {
    uint32_t r;
    asm("cvt.rn.bf16x2.f32 %0, %1, %2;" : "=r"(r) : "f"(hi), "f"(lo));
    return r;
}
__device__ __forceinline__ void cp_async16(uint32_t dst, const void* src) {
    asm volatile("cp.async.cg.shared.global [%0], [%1], 16;" :: "r"(dst), "l"(src));
}
__device__ __forceinline__ void cp_commit() { asm volatile("cp.async.commit_group;"); }
template<int N>
__device__ __forceinline__ void cp_wait() { asm volatile("cp.async.wait_group %0;" :: "n"(N)); }

__device__ __forceinline__ void ldm_x4(uint32_t* r, uint32_t a) {
    asm volatile("ldmatrix.sync.aligned.m8n8.x4.shared.b16 {%0,%1,%2,%3}, [%4];"
        : "=r"(r[0]), "=r"(r[1]), "=r"(r[2]), "=r"(r[3]) : "r"(a));
}
__device__ __forceinline__ void ldm_x4_t(uint32_t* r, uint32_t a) {
    asm volatile("ldmatrix.sync.aligned.m8n8.x4.trans.shared.b16 {%0,%1,%2,%3}, [%4];"
        : "=r"(r[0]), "=r"(r[1]), "=r"(r[2]), "=r"(r[3]) : "r"(a));
}
__device__ __forceinline__ void mma16816(float* d, const uint32_t* a, uint32_t b0, uint32_t b1) {
    asm volatile("mma.sync.aligned.m16n8k16.row.col.f32.bf16.bf16.f32 "
        "{%0,%1,%2,%3}, {%4,%5,%6,%7}, {%8,%9}, {%0,%1,%2,%3};"
        : "+f"(d[0]), "+f"(d[1]), "+f"(d[2]), "+f"(d[3])
        : "r"(a[0]), "r"(a[1]), "r"(a[2]), "r"(a[3]), "r"(b0), "r"(b1));
}
__device__ __forceinline__ float gelu_exact(float x) {
    return 0.5f * x * (1.0f + erff(x * 0.70710678118654752f));
}

// ---------------- fp32 -> bf16 weight convert, all 4 weights in one launch -----
__global__ void convw_kernel(const float* __restrict__ w0, __nv_bfloat16* __restrict__ t0,
                             const float* __restrict__ w1, __nv_bfloat16* __restrict__ t1,
                             const float* __restrict__ w2, __nv_bfloat16* __restrict__ t2,
                             const float* __restrict__ w3, __nv_bfloat16* __restrict__ t3) {
    int i = blockIdx.x * 256 + threadIdx.x;
    const float* w; __nv_bfloat16* t; int base;
    if (i < 12288)      { w = w0; t = t0; base = 0; }
    else if (i < 16384) { w = w1; t = t1; base = 12288; }
    else if (i < 32768) { w = w2; t = t2; base = 16384; }
    else                { w = w3; t = t3; base = 32768; }
    int j = i - base;
    float4 v = ((const float4*)w)[j];
    uint2 p;
    p.x = pack_bf16(v.x, v.y);
    p.y = pack_bf16(v.z, v.w);
    *(uint2*)(t + (size_t)j * 4) = p;
}

// ---------------- LayerNorm (one warp per token) + window permute --------------
__global__ void ln_kernel(const float* __restrict__ x, const float* __restrict__ g,
                          const float* __restrict__ b, __nv_bfloat16* __restrict__ out) {
    int warp = threadIdx.x >> 5;
    int lane = threadIdx.x & 31;
    int t = blockIdx.x * 8 + warp;
    float4 v = ((const float4*)(x + (size_t)t * CCH))[lane];
    float s  = v.x + v.y + v.z + v.w;
    float sq = v.x*v.x + v.y*v.y + v.z*v.z + v.w*v.w;
    #pragma unroll
    for (int o = 16; o; o >>= 1) {
        s  += __shfl_xor_sync(0xffffffffu, s,  o);
        sq += __shfl_xor_sync(0xffffffffu, sq, o);
    }
    float mean = s * (1.0f / CCH);
    float var  = sq * (1.0f / CCH) - mean * mean;
    float rstd = rsqrtf(var + EPSV);
    float4 gv = ((const float4*)g)[lane];
    float4 bv = ((const float4*)b)[lane];
    float rx = (v.x - mean) * rstd * gv.x + bv.x;
    float ry = (v.y - mean) * rstd * gv.y + bv.y;
    float rz = (v.z - mean) * rstd * gv.z + bv.z;
    float rw = (v.w - mean) * rstd * gv.w + bv.w;
    int bi = t >> 16;
    int oh = (t >> 8) & 255;
    int ow = t & 255;
    int sh = (oh + 252) & 255;
    int sw = (ow + 252) & 255;
    int wh = sh >> 3, ii = sh & 7;
    int wc = sw >> 3, jj = sw & 7;
    int win = (bi * 32 + wh) * 32 + wc;
    size_t ot = (size_t)win * 64 + ii * 8 + jj;
    uint2 pk;
    pk.x = pack_bf16(rx, ry);
    pk.y = pack_bf16(rz, rw);
    *(uint2*)(out + ot * CCH + lane * 4) = pk;
}

// ---------------- HMMA GEMM (proj only): BM=128 BN=128 BK=32 + LN2 fusion ------
__global__ __launch_bounds__(256) void proj_gemm(
    const __nv_bfloat16* __restrict__ A, const __nv_bfloat16* __restrict__ Bw,
    const float* __restrict__ bias, const float* __restrict__ extra, float* __restrict__ Cout,
    const float* __restrict__ g2, const float* __restrict__ b2, __nv_bfloat16* __restrict__ h2out)
{
    const int N = 128, K = 128;
    __shared__ __align__(128) __nv_bfloat16 As[2][128 * 32];
    __shared__ __align__(128) __nv_bfloat16 Bs[2][32 * 128];
    __shared__ float2 lnstat[128][2];

    const int tid  = threadIdx.x;
    const int lane = tid & 31;
    const int wid  = tid >> 5;
    const int wm   = wid & 3;
    const int wn   = wid >> 2;
    const int bm   = blockIdx.y * 128;

    const uint32_t s_a0 = smem_u32(As[0]);
    const uint32_t s_b0 = smem_u32(Bs[0]);

    auto load_chunk = [&](int c, int buf) {
        uint32_t abase = s_a0 + buf * 8192;
        #pragma unroll
        for (int r = 0; r < 2; r++) {
            int s = tid + r * 256;
            int row = s >> 2, seg = s & 3;
            cp_async16(abase + row * 64 + ((seg ^ ((row >> 1) & 3)) << 4),
                       A + (size_t)(bm + row) * K + c * 32 + seg * 8);
        }
        uint32_t bbase = s_b0 + buf * 8192;
        #pragma unroll
        for (int r = 0; r < 2; r++) {
            int s = tid + r * 256;
            int row = s >> 4, seg = s & 15;
            cp_async16(bbase + row * 256 + ((seg ^ (row & 7)) << 4),
                       Bw + (size_t)(c * 32 + row) * N + seg * 8);
        }
    };

    float d[2][8][4];
    #pragma unroll
    for (int mi = 0; mi < 2; mi++)
        #pragma unroll
        for (int ni = 0; ni < 8; ni++)
            #pragma unroll
            for (int r = 0; r < 4; r++) d[mi][ni][r] = 0.0f;

    load_chunk(0, 0);
    cp_commit();

    const int lrow = lane & 15;
    const int lseg = lane >> 4;

    for (int c = 0; c < 4; c++) {
        int buf = c & 1;
        if (c + 1 < 4) { load_chunk(c + 1, buf ^ 1); cp_commit(); cp_wait<1>(); }
        else cp_wait<0>();
        __syncthreads();
        uint32_t abase = s_a0 + buf * 8192;
        uint32_t bbase = s_b0 + buf * 8192;
        #pragma unroll
        for (int ks = 0; ks < 2; ks++) {
            uint32_t a[2][4];
            #pragma unroll
            for (int mi = 0; mi < 2; mi++) {
                int row = wm * 32 + mi * 16 + lrow;
                int seg = ks * 2 + lseg;
                ldm_x4(a[mi], abase + row * 64 + ((seg ^ ((row >> 1) & 3)) << 4));
            }
            uint32_t b[4][4];
            #pragma unroll
            for (int bp = 0; bp < 4; bp++) {
                int row = ks * 16 + lrow;
                int seg = wn * 8 + bp * 2 + lseg;
                ldm_x4_t(b[bp], bbase + row * 256 + ((seg ^ (row & 7)) << 4));
            }
            #pragma unroll
            for (int mi = 0; mi < 2; mi++)
                #pragma unroll
                for (int ni = 0; ni < 8; ni++)
                    mma16816(d[mi][ni], a[mi], b[ni >> 1][(ni & 1) * 2], b[ni >> 1][(ni & 1) * 2 + 1]);
        }
        __syncthreads();
    }

    const int l4 = lane >> 2, lm = lane & 3;
    float2 bs[8];
    #pragma unroll
    for (int ni = 0; ni < 8; ni++)
        bs[ni] = *(const float2*)(bias + wn * 64 + ni * 8 + lm * 2);

    size_t orows[2][2];
    #pragma unroll
    for (int mi = 0; mi < 2; mi++) {
        #pragma unroll
        for (int half = 0; half < 2; half++) {
            int row = bm + wm * 32 + mi * 16 + half * 8 + l4;
            int win = row >> 6, r6 = row & 63;
            int bi = win >> 10, wim = win & 1023;
            int wh = wim >> 5, wc = wim & 31;
            int ii = r6 >> 3, jj = r6 & 7;
            int oh = (wh * 8 + ii + 4) & 255;
            int ow = (wc * 8 + jj + 4) & 255;
            size_t orow = ((size_t)(bi * 256 + oh) * 256 + ow);
            orows[mi][half] = orow;
            float s = 0.0f, sq = 0.0f;
            #pragma unroll
            for (int ni = 0; ni < 8; ni++) {
                int col = wn * 64 + ni * 8 + lm * 2;
                float2 xr = *(const float2*)(extra + orow * 128 + col);
                float v0 = d[mi][ni][half * 2 + 0] + bs[ni].x + xr.x;
                float v1 = d[mi][ni][half * 2 + 1] + bs[ni].y + xr.y;
                d[mi][ni][half * 2 + 0] = v0;
                d[mi][ni][half * 2 + 1] = v1;
                s  += v0 + v1;
                sq += v0 * v0 + v1 * v1;
                float2 v; v.x = v0; v.y = v1;
                *(float2*)(Cout + orow * 128 + col) = v;
            }
            s  += __shfl_xor_sync(0xffffffffu, s,  1);
            sq += __shfl_xor_sync(0xffffffffu, sq, 1);
            s  += __shfl_xor_sync(0xffffffffu, s,  2);
            sq += __shfl_xor_sync(0xffffffffu, sq, 2);
            if (lm == 0) {
                float2 st; st.x = s; st.y = sq;
                lnstat[row - bm][wn] = st;
            }
        }
    }
    __syncthreads();
    float2 g2v[8], b2v[8];
    #pragma unroll
    for (int ni = 0; ni < 8; ni++) {
        g2v[ni] = *(const float2*)(g2 + wn * 64 + ni * 8 + lm * 2);
        b2v[ni] = *(const float2*)(b2 + wn * 64 + ni * 8 + lm * 2);
    }
    #pragma unroll
    for (int mi = 0; mi < 2; mi++) {
        #pragma unroll
        for (int half = 0; half < 2; half++) {
            int rl = wm * 32 + mi * 16 + half * 8 + l4;
            float2 sa = lnstat[rl][0], sb = lnstat[rl][1];
            float mean = (sa.x + sb.x) * (1.0f / CCH);
            float var  = (sa.y + sb.y) * (1.0f / CCH) - mean * mean;
            float rstd = rsqrtf(var + EPSV);
            size_t orow = orows[mi][half];
            #pragma unroll
            for (int ni = 0; ni < 8; ni++) {
                int col = wn * 64 + ni * 8 + lm * 2;
                float h0 = (d[mi][ni][half * 2 + 0] - mean) * rstd * g2v[ni].x + b2v[ni].x;
                float h1 = (d[mi][ni][half * 2 + 1] - mean) * rstd * g2v[ni].y + b2v[ni].y;
                *(uint32_t*)(h2out + orow * 128 + col) = pack_bf16(h0, h1);
            }
        }
    }
}

// ---------------- fused qkv GEMM + window attention ----------------------------
// block = 128 tokens = 2 windows. qkv computed into smem, attention from smem.
#define FQ_AOFF 0            // A (xw) tile: 128 rows x 256B, swizzled
#define FQ_BOFF 32768        // B double buffer: 2 x 8KB
#define FQ_QOFF 49152        // q region: 128 rows x 256B (swizzled)
#define FQ_KOFF 81920
#define FQ_VOFF 114688
#define FQ_TOFF 147456       // rpb table: 900 floats
#define FQ_LOFF 151056       // labels: 128 ints
#define FQ_JOFF 151568       // joff: 64 ints
#define FQ_SMEM 151824

__global__ __launch_bounds__(256) void fused_qkv_attn(
    const __nv_bfloat16* __restrict__ xw, const __nv_bfloat16* __restrict__ wq,
    const float* __restrict__ qkvb, const float* __restrict__ rpb,
    __nv_bfloat16* __restrict__ out)
{
    extern __shared__ char sm[];
    float* tbl  = (float*)(sm + FQ_TOFF);
    int*   lab  = (int*)(sm + FQ_LOFF);
    int*   joff = (int*)(sm + FQ_JOFF);

    const int tid  = threadIdx.x;
    const int lane = tid & 31;
    const int wid  = tid >> 5;
    const int wm   = wid & 3;
    const int wn   = wid >> 2;
    const int bm   = blockIdx.x * 128;

    const uint32_t s_base = smem_u32(sm);
    const uint32_t s_a = s_base + FQ_AOFF;
    const uint32_t s_b = s_base + FQ_BOFF;

    // A tile: 128 rows x 16 segs (16B each)
    #pragma unroll
    for (int u = 0; u < 8; u++) {
        int s = u * 256 + tid;
        int row = s >> 4, seg = s & 15;
        cp_async16(s_a + row * 256 + ((seg ^ (row & 7)) << 4),
                   xw + (size_t)(bm + row) * 128 + seg * 8);
    }
    auto load_b = [&](int t, int buf) {
        uint32_t bbase = s_b + buf * 8192;
        #pragma unroll
        for (int r2 = 0; r2 < 2; r2++) {
            int s = tid + r2 * 256;
            int row = s >> 4, seg = s & 15;
            cp_async16(bbase + row * 256 + ((seg ^ (row & 7)) << 4),
                       wq + (size_t)((t & 3) * 32 + row) * 384 + (t >> 2) * 128 + seg * 8);
        }
    };
    load_b(0, 0);
    cp_commit();

    for (int p = tid; p < 900; p += 256) tbl[p] = rpb[p];
    if (tid < 64) joff[tid] = (-(tid >> 3) * 15 - (tid & 7)) * 4;
    if (tid < 128) {
        int wim = (blockIdx.x * 2 + (tid >> 6)) & 1023;
        int r = (wim >> 5) * 8 + ((tid & 63) >> 3);
        int c = (wim & 31) * 8 + (tid & 7);
        int rr = (r < 248) ? 0 : ((r < 252) ? 1 : 2);
        int rc = (c < 248) ? 0 : ((c < 252) ? 1 : 2);
        lab[tid] = rr * 3 + rc;
    }

    const int lrow = lane & 15;
    const int lseg = lane >> 4;
    const int l4 = lane >> 2, lm = lane & 3;

    float d[2][8][4];
    #pragma unroll
    for (int mi = 0; mi < 2; mi++)
        #pragma unroll
        for (int ni = 0; ni < 8; ni++)
            #pragma unroll
            for (int r = 0; r < 4; r++) d[mi][ni][r] = 0.0f;

    // ---- qkv GEMM: 12 flat chunks (3 column blocks x 4 K-chunks) ----
    for (int t = 0; t < 12; t++) {
        int buf = t & 1;
        if (t < 11) { load_b(t + 1, buf ^ 1); cp_commit(); cp_wait<1>(); }
        else cp_wait<0>();
        __syncthreads();
        uint32_t bbase = s_b + buf * 8192;
        #pragma unroll
        for (int ks = 0; ks < 2; ks++) {
            uint32_t a[2][4];
            #pragma unroll
            for (int mi = 0; mi < 2; mi++) {
                int row = wm * 32 + mi * 16 + lrow;
                int seg = (t & 3) * 4 + ks * 2 + lseg;
                ldm_x4(a[mi], s_a + row * 256 + ((seg ^ (row & 7)) << 4));
            }
            uint32_t b[4][4];
            #pragma unroll
            for (int bp = 0; bp < 4; bp++) {
                int row = ks * 16 + lrow;
                int seg = wn * 8 + bp * 2 + lseg;
                ldm_x4_t(b[bp], bbase + row * 256 + ((seg ^ (row & 7)) << 4));
            }
            #pragma unroll
            for (int mi = 0; mi < 2; mi++)
                #pragma unroll
                for (int ni = 0; ni < 8; ni++)
                    mma16816(d[mi][ni], a[mi], b[ni >> 1][(ni & 1) * 2], b[ni >> 1][(ni & 1) * 2 + 1]);
        }
        __syncthreads();
        if ((t & 3) == 3) {
            int bn = t >> 2;   // 0=q 1=k 2=v
            char* region = sm + FQ_QOFF + bn * 32768;
            #pragma unroll
            for (int mi = 0; mi < 2; mi++) {
                #pragma unroll
                for (int half = 0; half < 2; half++) {
                    int row = wm * 32 + mi * 16 + half * 8 + l4;
                    #pragma unroll
                    for (int ni = 0; ni < 8; ni++) {
                        int col = wn * 64 + ni * 8 + lm * 2;
                        float2 bsv = *(const float2*)(qkvb + bn * 128 + col);
                        float v0 = d[mi][ni][half * 2 + 0] + bsv.x;
                        float v1 = d[mi][ni][half * 2 + 1] + bsv.y;
                        *(uint32_t*)(region + row * 256 + (((col >> 3) ^ (row & 7)) << 4) + (col & 7) * 2)
                            = pack_bf16(v0, v1);
                        d[mi][ni][half * 2 + 0] = 0.0f;
                        d[mi][ni][half * 2 + 1] = 0.0f;
                    }
                }
            }
        }
    }
    __syncthreads();

    // ---- attention: 2 windows sequentially; warp = (head, row-half) ----
    const uint32_t s_q = s_base + FQ_QOFF;
    const uint32_t s_k = s_base + FQ_KOFF;
    const uint32_t s_v = s_base + FQ_VOFF;
    const int h = wid >> 1, hhalf = wid & 1;
    const int mbase = hhalf * 32;
    const float scale = 0.17677669529663687f;

    for (int w = 0; w < 2; w++) {
        int wbase = w * 64;
        int wim = (blockIdx.x * 2 + w) & 1023;
        bool masked = ((wim >> 5) == 31) || ((wim & 31) == 31);

        float S[2][8][4];
        #pragma unroll
        for (int mi = 0; mi < 2; mi++)
            #pragma unroll
            for (int ni = 0; ni < 8; ni++)
                #pragma unroll
                for (int r = 0; r < 4; r++) S[mi][ni][r] = 0.0f;

        #pragma unroll
        for (int ks = 0; ks < 2; ks++) {
            uint32_t a[2][4], b[4][4];
            #pragma unroll
            for (int mi = 0; mi < 2; mi++) {
                int row = wbase + mbase + mi * 16 + lrow;
                int seg = h * 4 + ks * 2 + lseg;
                ldm_x4(a[mi], s_q + row * 256 + ((seg ^ (row & 7)) << 4));
            }
            #pragma unroll
            for (int nt = 0; nt < 4; nt++) {
                int row = wbase + nt * 16 + lrow;
                int seg = h * 4 + ks * 2 + lseg;
                ldm_x4(b[nt], s_k + row * 256 + ((seg ^ (row & 7)) << 4));
            }
            #pragma unroll
            for (int mi = 0; mi < 2; mi++)
                #pragma unroll
                for (int ni = 0; ni < 8; ni++)
                    mma16816(S[mi][ni], a[mi], b[ni >> 1][ni & 1], b[ni >> 1][(ni & 1) + 2]);
        }

        float sum[2][2];
        #pragma unroll
        for (int mi = 0; mi < 2; mi++) {
            #pragma unroll
            for (int rr = 0; rr < 2; rr++) {
                int i = mbase + mi * 16 + rr * 8 + l4;
                int rowbase = (((i >> 3) + 7) * 15 + ((i & 7) + 7)) * 4 + h;
                int li = lab[wbase + i];
                float m = -1e30f;
                #pragma unroll
                for (int ni = 0; ni < 8; ni++) {
                    int j0 = ni * 8 + lm * 2;
                    int idx0 = rowbase + joff[j0];
                    float v0 = S[mi][ni][rr * 2 + 0] * scale + tbl[idx0];
                    float v1 = S[mi][ni][rr * 2 + 1] * scale + tbl[idx0 - 4];
                    if (masked) {
                        if (lab[wbase + j0] != li)     v0 -= 100.0f;
                        if (lab[wbase + j0 + 1] != li) v1 -= 100.0f;
                    }
                    S[mi][ni][rr * 2 + 0] = v0;
                    S[mi][ni][rr * 2 + 1] = v1;
                    m = fmaxf(m, fmaxf(v0, v1));
                }
                m = fmaxf(m, __shfl_xor_sync(0xffffffffu, m, 1));
                m = fmaxf(m, __shfl_xor_sync(0xffffffffu, m, 2));
                float sm_ = 0.0f;
                #pragma unroll
                for (int ni = 0; ni < 8; ni++) {
                    #pragma unroll
                    for (int e = 0; e < 2; e++) {
                        float ev = __expf(S[mi][ni][rr * 2 + e] - m);
                        S[mi][ni][rr * 2 + e] = ev;
                        sm_ += ev;
                    }
                }
                sm_ += __shfl_xor_sync(0xffffffffu, sm_, 1);
                sm_ += __shfl_xor_sync(0xffffffffu, sm_, 2);
                sum[mi][rr] = sm_;
            }
        }

        uint32_t P[2][8][2];
        #pragma unroll
        for (int mi = 0; mi < 2; mi++)
            #pragma unroll
            for (int ni = 0; ni < 8; ni++) {
                P[mi][ni][0] = pack_bf16(S[mi][ni][0], S[mi][ni][1]);
                P[mi][ni][1] = pack_bf16(S[mi][ni][2], S[mi][ni][3]);
            }

        float o[2][4][4];
        #pragma unroll
        for (int mi = 0; mi < 2; mi++)
            #pragma unroll
            for (int nd = 0; nd < 4; nd++)
                #pragma unroll
                for (int r = 0; r < 4; r++) o[mi][nd][r] = 0.0f;

        #pragma unroll
        for (int kn = 0; kn < 4; kn++) {
            uint32_t vb[2][4];
            #pragma unroll
            for (int vp = 0; vp < 2; vp++) {
                int row = wbase + kn * 16 + lrow;
                int seg = h * 4 + vp * 2 + lseg;
                ldm_x4_t(vb[vp], s_v + row * 256 + ((seg ^ (row & 7)) << 4));
            }
            #pragma unroll
            for (int mi = 0; mi < 2; mi++) {
                uint32_t a[4] = { P[mi][2 * kn][0], P[mi][2 * kn][1],
                                  P[mi][2 * kn + 1][0], P[mi][2 * kn + 1][1] };
                #pragma unroll
                for (int nd = 0; nd < 4; nd++)
                    mma16816(o[mi][nd], a, vb[nd >> 1][(nd & 1) * 2], vb[nd >> 1][(nd & 1) * 2 + 1]);
            }
        }

        #pragma unroll
        for (int mi = 0; mi < 2; mi++) {
            #pragma unroll
            for (int rr = 0; rr < 2; rr++) {
                float inv = 1.0f / sum[mi][rr];
                size_t row = (size_t)(bm + wbase + mbase + mi * 16 + rr * 8 + l4);
                #pragma unroll
                for (int nd = 0; nd < 4; nd++) {
                    int col = h * 32 + nd * 8 + lm * 2;
                    *(uint32_t*)(out + row * 128 + col) =
                        pack_bf16(o[mi][nd][rr * 2] * inv, o[mi][nd][rr * 2 + 1] * inv);
                }
            }
        }
    }
}

// ---------------- fused MLP: fc1 + GELU + fc2 + residual -----------------------
// block = 128 tokens; m1 tile (128x512 bf16) stays in smem.
#define ML_AOFF 0            // h2 tile: 128 x 256B (swizzled)
#define ML_MOFF 32768        // m1: 128 x 1024B (swizzled)
#define ML_BOFF 163840       // B double buffer: 2 x 8KB
#define ML_SMEM 180224

__global__ __launch_bounds__(256) void fused_mlp(
    const __nv_bfloat16* __restrict__ h2, const __nv_bfloat16* __restrict__ w1b,
    const float* __restrict__ b1, const __nv_bfloat16* __restrict__ w2b,
    const float* __restrict__ b2, const float* __restrict__ y1, float* __restrict__ out)
{
    extern __shared__ char sm[];
    const int tid  = threadIdx.x;
    const int lane = tid & 31;
    const int wid  = tid >> 5;
    const int wm   = wid & 3;
    const int wn   = wid >> 2;
    const int bm   = blockIdx.x * 128;

    const uint32_t s_base = smem_u32(sm);
    const uint32_t s_a = s_base + ML_AOFF;
    const uint32_t s_m = s_base + ML_MOFF;
    const uint32_t s_b = s_base + ML_BOFF;

    // A (h2) tile: 128 rows x 16 segs
    #pragma unroll
    for (int u = 0; u < 8; u++) {
        int s = u * 256 + tid;
        int row = s >> 4, seg = s & 15;
        cp_async16(s_a + row * 256 + ((seg ^ (row & 7)) << 4),
                   h2 + (size_t)(bm + row) * 128 + seg * 8);
    }
    auto load_b1 = [&](int t, int buf) {
        uint32_t bbase = s_b + buf * 8192;
        #pragma unroll
        for (int r2 = 0; r2 < 2; r2++) {
            int s = tid + r2 * 256;
            int row = s >> 4, seg = s & 15;
            cp_async16(bbase + row * 256 + ((seg ^ (row & 7)) << 4),
                       w1b + (size_t)((t & 3) * 32 + row) * 512 + (t >> 2) * 128 + seg * 8);
        }
    };
    auto load_b2 = [&](int c, int buf) {
        uint32_t bbase = s_b + buf * 8192;
        #pragma unroll
        for (int r2 = 0; r2 < 2; r2++) {
            int s = tid + r2 * 256;
            int row = s >> 4, seg = s & 15;
            cp_async16(bbase + row * 256 + ((seg ^ (row & 7)) << 4),
                       w2b + (size_t)(c * 32 + row) * 128 + seg * 8);
        }
    };
    load_b1(0, 0);
    cp_commit();

    const int lrow = lane & 15;
    const int lseg = lane >> 4;
    const int l4 = lane >> 2, lm = lane & 3;

    float d[2][8][4];
    #pragma unroll
    for (int mi = 0; mi < 2; mi++)
        #pragma unroll
        for (int ni = 0; ni < 8; ni++)
            #pragma unroll
            for (int r = 0; r < 4; r++) d[mi][ni][r] = 0.0f;

    // ---- phase 1: m1 = gelu(h2 @ w1 + b1) -> smem, 16 flat chunks ----
    for (int t = 0; t < 16; t++) {
        int buf = t & 1;
        if (t < 15) { load_b1(t + 1, buf ^ 1); cp_commit(); cp_wait<1>(); }
        else cp_wait<0>();
        __syncthreads();
        uint32_t bbase = s_b + buf * 8192;
        #pragma unroll
        for (int ks = 0; ks < 2; ks++) {
            uint32_t a[2][4];
            #pragma unroll
            for (int mi = 0; mi < 2; mi++) {
                int row = wm * 32 + mi * 16 + lrow;
                int seg = (t & 3) * 4 + ks * 2 + lseg;
                ldm_x4(a[mi], s_a + row * 256 + ((seg ^ (row & 7)) << 4));
            }
            uint32_t b[4][4];
            #pragma unroll
            for (int bp = 0; bp < 4; bp++) {
                int row = ks * 16 + lrow;
                int seg = wn * 8 + bp * 2 + lseg;
                ldm_x4_t(b[bp], bbase + row * 256 + ((seg ^ (row & 7)) << 4));
            }
            #pragma unroll
            for (int mi = 0; mi < 2; mi++)
                #pragma unroll
                for (int ni = 0; ni < 8; ni++)
                    mma16816(d[mi][ni], a[mi], b[ni >> 1][(ni & 1) * 2], b[ni >> 1][(ni & 1) * 2 + 1]);
        }
        __syncthreads();
        if ((t & 3) == 3) {
            int nc = t >> 2;
            #pragma unroll
            for (int mi = 0; mi < 2; mi++) {
                #pragma unroll
                for (int half = 0; half < 2; half++) {
                    int row = wm * 32 + mi * 16 + half * 8 + l4;
                    #pragma unroll
                    for (int ni = 0; ni < 8; ni++) {
                        int col = nc * 128 + wn * 64 + ni * 8 + lm * 2;
                        float2 bsv = *(const float2*)(b1 + col);
                        float v0 = gelu_exact(d[mi][ni][half * 2 + 0] + bsv.x);
                        float v1 = gelu_exact(d[mi][ni][half * 2 + 1] + bsv.y);
                        *(uint32_t*)(sm + ML_MOFF + row * 1024 + (((col >> 3) ^ (row & 7)) << 4) + (col & 7) * 2)
                            = pack_bf16(v0, v1);
                        d[mi][ni][half * 2 + 0] = 0.0f;
                        d[mi][ni][half * 2 + 1] = 0.0f;
                    }
                }
            }
        }
    }
    __syncthreads();

    // ---- phase 2: out = m1 @ w2 + b2 + y1 (K=512, 16 chunks) ----
    load_b2(0, 0);
    cp_commit();
    for (int c = 0; c < 16; c++) {
        int buf = c & 1;
        if (c + 1 < 16) { load_b2(c + 1, buf ^ 1); cp_commit(); cp_wait<1>(); }
        else cp_wait<0>();
        __syncthreads();
        uint32_t bbase = s_b + buf * 8192;
        #pragma unroll
        for (int ks = 0; ks < 2; ks++) {
            uint32_t a[2][4];
            #pragma unroll
            for (int mi = 0; mi < 2; mi++) {
                int row = wm * 32 + mi * 16 + lrow;
                int seg = c * 4 + ks * 2 + lseg;
                ldm_x4(a[mi], s_m + row * 1024 + ((seg ^ (row & 7)) << 4));
            }
            uint32_t b[4][4];
            #pragma unroll
            for (int bp = 0; bp < 4; bp++) {
                int row = ks * 16 + lrow;
                int seg = wn * 8 + bp * 2 + lseg;
                ldm_x4_t(b[bp], bbase + row * 256 + ((seg ^ (row & 7)) << 4));
            }
            #pragma unroll
            for (int mi = 0; mi < 2; mi++)
                #pragma unroll
                for (int ni = 0; ni < 8; ni++)
                    mma16816(d[mi][ni], a[mi], b[ni >> 1][(ni & 1) * 2], b[ni >> 1][(ni & 1) * 2 + 1]);
        }
        __syncthreads();
    }

    float2 bs[8];
    #pragma unroll
    for (int ni = 0; ni < 8; ni++)
        bs[ni] = *(const float2*)(b2 + wn * 64 + ni * 8 + lm * 2);
    #pragma unroll
    for (int mi = 0; mi < 2; mi++) {
        #pragma unroll
        for (int half = 0; half < 2; half++) {
            int row = bm + wm * 32 + mi * 16 + half * 8 + l4;
            #pragma unroll
            for (int ni = 0; ni < 8; ni++) {
                int col = wn * 64 + ni * 8 + lm * 2;
                float2 res = *(const float2*)(y1 + (size_t)row * 128 + col);
                float2 v;
                v.x = d[mi][ni][half * 2 + 0] + bs[ni].x + res.x;
                v.y = d[mi][ni][half * 2 + 1] + bs[ni].y + res.y;
                *(float2*)(out + (size_t)row * 128 + col) = v;
            }
        }
    }
}

// ---------------- launch ----------------
extern "C" void kernel_launch(void* const* d_in, const int* in_sizes, int n_in,
                              void* d_out, int out_size) {
    const float* x      = (const float*)d_in[0];
    const float* gamma1 = (const float*)d_in[1];
    const float* beta1  = (const float*)d_in[2];
    const float* qkv_w  = (const float*)d_in[3];
    const float* qkv_b  = (const float*)d_in[4];
    const float* proj_w = (const float*)d_in[5];
    const float* proj_b = (const float*)d_in[6];
    const float* rpb    = (const float*)d_in[7];
    const float* gamma2 = (const float*)d_in[8];
    const float* beta2  = (const float*)d_in[9];
    const float* w1     = (const float*)d_in[10];
    const float* b1     = (const float*)d_in[11];
    const float* w2     = (const float*)d_in[12];
    const float* b2     = (const float*)d_in[13];
    float* out = (float*)d_out;

    __nv_bfloat16 *xw, *att, *h2, *wq, *wp, *w1b, *w2b;
    float *y1;
    cudaGetSymbolAddress((void**)&xw,  g_xw);
    cudaGetSymbolAddress((void**)&att, g_att);
    cudaGetSymbolAddress((void**)&y1,  g_y1);
    cudaGetSymbolAddress((void**)&h2,  g_h2);
    cudaGetSymbolAddress((void**)&wq,  g_wq);
    cudaGetSymbolAddress((void**)&wp,  g_wp);
    cudaGetSymbolAddress((void**)&w1b, g_w1b);
    cudaGetSymbolAddress((void**)&w2b, g_w2b);

    cudaFuncSetAttribute(fused_qkv_attn, cudaFuncAttributeMaxDynamicSharedMemorySize, FQ_SMEM);
    cudaFuncSetAttribute(fused_mlp, cudaFuncAttributeMaxDynamicSharedMemorySize, ML_SMEM);

    // bf16 weight conversion (one launch, layouts preserved)
    convw_kernel<<<49152 / 256, 256>>>(qkv_w, wq, proj_w, wp, w1, w1b, w2, w2b);

    // 1. LN1 + shift + window partition (bf16)
    ln_kernel<<<TOK / 8, 256>>>(x, gamma1, beta1, xw);
    // 2. fused qkv GEMM + window attention
    fused_qkv_attn<<<TOK / 128, 256, FQ_SMEM>>>(xw, wq, qkv_b, rpb, att);
    // 3. proj GEMM + window reverse + residual -> y1 fp32, fused LN2 -> h2 bf16
    proj_gemm<<<dim3(1, TOK / 128), 256>>>(att, wp, proj_b, x, y1, gamma2, beta2, h2);
    // 4. fused MLP: fc1 + GELU + fc2 + residual -> out
    fused_mlp<<<TOK / 128, 256, ML_SMEM>>>(h2, w1b, b1, w2b, b2, y1, out);
}